// round 10
// baseline (speedup 1.0000x reference)
#include <cuda_runtime.h>
#include <cuda_bf16.h>
#include <cstdint>

#define L_ 6
#define D_ 1024
#define H_ 16
#define DK_ 64
#define F_ 4096
#define B_ 2
#define S_ 1024
#define T_ (B_*S_)

// ---------------- scratch (static device allocations) ----------------
__device__ float g_x  [T_*D_];
__device__ __nv_bfloat16 g_qkvh[3*T_*D_];
__device__ __nv_bfloat16 g_qkvl[3*T_*D_];
__device__ __nv_bfloat16 g_h_hi [T_*D_];
__device__ __nv_bfloat16 g_h_lo [T_*D_];
__device__ __nv_bfloat16 g_ao_hi[T_*D_];
__device__ __nv_bfloat16 g_ao_lo[T_*D_];
__device__ __nv_bfloat16 g_ff_hi[T_*F_];
__device__ __nv_bfloat16 g_ff_lo[T_*F_];

__device__ __nv_bfloat16 g_qkvT_hi[L_*3*D_*D_];
__device__ __nv_bfloat16 g_qkvT_lo[L_*3*D_*D_];
__device__ __nv_bfloat16 g_woT_hi [L_*D_*D_];
__device__ __nv_bfloat16 g_woT_lo [L_*D_*D_];
__device__ __nv_bfloat16 g_w1T_hi [L_*D_*F_];
__device__ __nv_bfloat16 g_w1T_lo [L_*D_*F_];
__device__ __nv_bfloat16 g_w2T_hi [L_*F_*D_];
__device__ __nv_bfloat16 g_w2T_lo [L_*F_*D_];

// ---------------- helpers ----------------
__device__ __forceinline__ uint32_t smem_u32(const void* p) {
    uint32_t a;
    asm("{ .reg .u64 t; cvta.to.shared.u64 t, %1; cvt.u32.u64 %0, t; }" : "=r"(a) : "l"(p));
    return a;
}
__device__ __forceinline__ uint32_t pack_hilo(float a, float b, uint32_t& lo) {
    __nv_bfloat16 ha = __float2bfloat16_rn(a);
    __nv_bfloat16 hb = __float2bfloat16_rn(b);
    __nv_bfloat16 la = __float2bfloat16_rn(a - __bfloat162float(ha));
    __nv_bfloat16 lb = __float2bfloat16_rn(b - __bfloat162float(hb));
    __nv_bfloat162 h2 = __halves2bfloat162(ha, hb);
    __nv_bfloat162 l2 = __halves2bfloat162(la, lb);
    lo = *reinterpret_cast<uint32_t*>(&l2);
    return *reinterpret_cast<uint32_t*>(&h2);
}

#define CP16(dst, src) \
    asm volatile("cp.async.cg.shared.global [%0], [%1], 16;" :: "r"(dst), "l"(src) : "memory")
#define CP_COMMIT() asm volatile("cp.async.commit_group;" ::: "memory")
#define CP_WAIT1()  asm volatile("cp.async.wait_group 1;"  ::: "memory")
#define CP_WAIT0()  asm volatile("cp.async.wait_group 0;"  ::: "memory")

#define LDSM4(r, addr) \
    asm volatile("ldmatrix.sync.aligned.m8n8.x4.shared.b16 {%0,%1,%2,%3}, [%4];" \
        : "=r"((r)[0]), "=r"((r)[1]), "=r"((r)[2]), "=r"((r)[3]) : "r"(addr))
#define LDSM4T(r, addr) \
    asm volatile("ldmatrix.sync.aligned.m8n8.x4.trans.shared.b16 {%0,%1,%2,%3}, [%4];" \
        : "=r"((r)[0]), "=r"((r)[1]), "=r"((r)[2]), "=r"((r)[3]) : "r"(addr))

#define MMA16816(c, a, b) \
    asm volatile("mma.sync.aligned.m16n8k16.row.col.f32.bf16.bf16.f32 " \
        "{%0,%1,%2,%3}, {%4,%5,%6,%7}, {%8,%9}, {%0,%1,%2,%3};" \
        : "+f"((c)[0]), "+f"((c)[1]), "+f"((c)[2]), "+f"((c)[3]) \
        : "r"((a)[0]), "r"((a)[1]), "r"((a)[2]), "r"((a)[3]), "r"((b)[0]), "r"((b)[1]))
#define MMA2(c, a, b0, b1) \
    asm volatile("mma.sync.aligned.m16n8k16.row.col.f32.bf16.bf16.f32 " \
        "{%0,%1,%2,%3}, {%4,%5,%6,%7}, {%8,%9}, {%0,%1,%2,%3};" \
        : "+f"((c)[0]), "+f"((c)[1]), "+f"((c)[2]), "+f"((c)[3]) \
        : "r"((a)[0]), "r"((a)[1]), "r"((a)[2]), "r"((a)[3]), "r"(b0), "r"(b1))

// ---------------- weight transpose + hi/lo split ----------------
__global__ void convT_kernel(const float* __restrict__ in, __nv_bfloat16* __restrict__ hi,
                             __nv_bfloat16* __restrict__ lo, int K, int N,
                             size_t in_ls, size_t out_ls) {
    __shared__ float t[32][33];
    in += (size_t)blockIdx.z * in_ls;
    hi += (size_t)blockIdx.z * out_ls;
    lo += (size_t)blockIdx.z * out_ls;
    int n0 = blockIdx.x * 32, k0 = blockIdx.y * 32;
    int tx = threadIdx.x, ty = threadIdx.y;
    #pragma unroll
    for (int i = 0; i < 4; i++)
        t[ty + 8*i][tx] = in[(size_t)(k0 + ty + 8*i) * N + n0 + tx];
    __syncthreads();
    #pragma unroll
    for (int i = 0; i < 4; i++) {
        float v = t[tx][ty + 8*i];
        __nv_bfloat16 h = __float2bfloat16_rn(v);
        __nv_bfloat16 l = __float2bfloat16_rn(v - __bfloat162float(h));
        size_t o = (size_t)(n0 + ty + 8*i) * K + k0 + tx;
        hi[o] = h; lo[o] = l;
    }
}

__global__ void convT_qkv(const float* __restrict__ wq, const float* __restrict__ wk,
                          const float* __restrict__ wv,
                          __nv_bfloat16* __restrict__ hi, __nv_bfloat16* __restrict__ lo) {
    __shared__ float t[32][33];
    int zz = blockIdx.z;
    int l = zz / 3, which = zz % 3;
    const float* in = (which == 0 ? wq : which == 1 ? wk : wv) + (size_t)l * D_ * D_;
    size_t ob = (size_t)l * 3 * D_ * D_ + (size_t)which * D_ * D_;
    int n0 = blockIdx.x * 32, k0 = blockIdx.y * 32;
    int tx = threadIdx.x, ty = threadIdx.y;
    #pragma unroll
    for (int i = 0; i < 4; i++)
        t[ty + 8*i][tx] = in[(size_t)(k0 + ty + 8*i) * D_ + n0 + tx];
    __syncthreads();
    #pragma unroll
    for (int i = 0; i < 4; i++) {
        float v = t[tx][ty + 8*i];
        __nv_bfloat16 h = __float2bfloat16_rn(v);
        __nv_bfloat16 l2 = __float2bfloat16_rn(v - __bfloat162float(h));
        size_t o = ob + (size_t)(n0 + ty + 8*i) * D_ + k0 + tx;
        hi[o] = h; lo[o] = l2;
    }
}

// ---------------- bf16 tensor-core GEMM (3-term split), 128x128, 2-stage ----------------
#define RS 80
#define GTILE (128*RS)
#define GBUF  (4*GTILE)
#define GSMEM_BYTES (2*GBUF)     // 81920 -> 2 CTAs/SM

template<int MODE>
__global__ void __launch_bounds__(256) mma_gemm(
    const __nv_bfloat16* __restrict__ Ah, const __nv_bfloat16* __restrict__ Al,
    const __nv_bfloat16* __restrict__ Bh, const __nv_bfloat16* __restrict__ Bl,
    const float* __restrict__ bias, const float* __restrict__ res,
    float* __restrict__ C, __nv_bfloat16* __restrict__ Ch, __nv_bfloat16* __restrict__ Cl,
    int M, int N, int K)
{
    extern __shared__ __align__(128) char smem[];
    const uint32_t sb = smem_u32(smem);
    const int tid = threadIdx.x, lane = tid & 31, wid = tid >> 5;
    const int wm = wid >> 2, wn = wid & 3;
    const int bm = blockIdx.y * 128, bn = blockIdx.x * 128;

    const int r0 = tid >> 2, u = tid & 3;
    const int r1 = r0 + 64;

    float c[4][4][4];
    #pragma unroll
    for (int i = 0; i < 4; i++)
        #pragma unroll
        for (int j = 0; j < 4; j++)
            #pragma unroll
            for (int q = 0; q < 4; q++) c[i][j][q] = 0.f;

    const int NT = K >> 5;

    auto issue = [&](int kt, int buf) {
        const int k0 = kt << 5;
        uint32_t d = sb + buf * GBUF;
        const size_t ga0 = (size_t)(bm + r0) * K + k0 + u * 8;
        const size_t ga1 = (size_t)(bm + r1) * K + k0 + u * 8;
        const size_t gb0 = (size_t)(bn + r0) * K + k0 + u * 8;
        const size_t gb1 = (size_t)(bn + r1) * K + k0 + u * 8;
        const uint32_t o0 = r0 * RS + u * 16, o1 = r1 * RS + u * 16;
        CP16(d + o0,             Ah + ga0);  CP16(d + o1,             Ah + ga1);
        CP16(d + GTILE   + o0,   Al + ga0);  CP16(d + GTILE   + o1,   Al + ga1);
        CP16(d + 2*GTILE + o0,   Bh + gb0);  CP16(d + 2*GTILE + o1,   Bh + gb1);
        CP16(d + 3*GTILE + o0,   Bl + gb0);  CP16(d + 3*GTILE + o1,   Bl + gb1);
    };

    const int lrow = lane & 7;
    const int lsel = lane >> 3;
    const uint32_t aoff = (uint32_t)((wm * 64 + (lsel & 1) * 8 + lrow) * RS + (lsel >> 1) * 16);
    const uint32_t boff = (uint32_t)((wn * 32 + ((lane >> 4) & 1) * 8 + lrow) * RS + ((lane >> 3) & 1) * 16);

    issue(0, 0); CP_COMMIT();

    for (int kt = 0; kt < NT; kt++) {
        const int buf = kt & 1;
        if (kt + 1 < NT) { issue(kt + 1, buf ^ 1); CP_COMMIT(); CP_WAIT1(); }
        else             { CP_WAIT0(); }
        __syncthreads();

        const uint32_t base = sb + buf * GBUF;
        #pragma unroll
        for (int ks = 0; ks < 2; ks++) {
            uint32_t a_h[4][4], a_l[4][4], b_h[4][2], b_l[4][2];
            const uint32_t ka = base + aoff + ks * 32;
            #pragma unroll
            for (int mt = 0; mt < 4; mt++) {
                LDSM4(a_h[mt], ka + mt * (16 * RS));
                LDSM4(a_l[mt], ka + GTILE + mt * (16 * RS));
            }
            const uint32_t kb = base + 2*GTILE + boff + ks * 32;
            #pragma unroll
            for (int np = 0; np < 2; np++) {
                uint32_t t4h[4], t4l[4];
                LDSM4(t4h, kb + np * (16 * RS));
                LDSM4(t4l, kb + GTILE + np * (16 * RS));
                b_h[np*2][0]   = t4h[0]; b_h[np*2][1]   = t4h[1];
                b_h[np*2+1][0] = t4h[2]; b_h[np*2+1][1] = t4h[3];
                b_l[np*2][0]   = t4l[0]; b_l[np*2][1]   = t4l[1];
                b_l[np*2+1][0] = t4l[2]; b_l[np*2+1][1] = t4l[3];
            }
            #pragma unroll
            for (int mt = 0; mt < 4; mt++)
                #pragma unroll
                for (int nt = 0; nt < 4; nt++) {
                    MMA16816(c[mt][nt], a_h[mt], b_h[nt]);
                    MMA16816(c[mt][nt], a_h[mt], b_l[nt]);
                    MMA16816(c[mt][nt], a_l[mt], b_h[nt]);
                }
        }
        __syncthreads();
    }

    const int g = lane >> 2, t4 = lane & 3;
    #pragma unroll
    for (int mt = 0; mt < 4; mt++) {
        #pragma unroll
        for (int nt = 0; nt < 4; nt++) {
            int row = bm + wm * 64 + mt * 16 + g;
            int col = bn + wn * 32 + nt * 8 + t4 * 2;
            float v0 = c[mt][nt][0], v1 = c[mt][nt][1];
            float v2 = c[mt][nt][2], v3 = c[mt][nt][3];
            if (MODE == 2) {
                float b0 = bias[col], b1 = bias[col + 1];
                v0 = fmaxf(v0 + b0, 0.f); v1 = fmaxf(v1 + b1, 0.f);
                v2 = fmaxf(v2 + b0, 0.f); v3 = fmaxf(v3 + b1, 0.f);
                uint32_t lo0, lo1;
                uint32_t hi0 = pack_hilo(v0, v1, lo0);
                uint32_t hi1 = pack_hilo(v2, v3, lo1);
                size_t o0 = (size_t)row * N + col;
                size_t o1 = (size_t)(row + 8) * N + col;
                *(uint32_t*)(Ch + o0) = hi0; *(uint32_t*)(Cl + o0) = lo0;
                *(uint32_t*)(Ch + o1) = hi1; *(uint32_t*)(Cl + o1) = lo1;
            } else if (MODE == 3) {
                float b0 = bias[col], b1 = bias[col + 1];
                size_t o0 = (size_t)row * N + col;
                size_t o1 = (size_t)(row + 8) * N + col;
                float2 r0v = *(const float2*)(res + o0);
                float2 r1v = *(const float2*)(res + o1);
                *(float2*)(C + o0) = make_float2(v0 + b0 + r0v.x, v1 + b1 + r0v.y);
                *(float2*)(C + o1) = make_float2(v2 + b0 + r1v.x, v3 + b1 + r1v.y);
            } else {
                int which = col >> 10;
                int h_ = (col >> 6) & 15;
                int d_ = col & 63;
                #pragma unroll
                for (int rr = 0; rr < 2; rr++) {
                    int grow = row + rr * 8;
                    int b_ = grow >> 10, s_ = grow & 1023;
                    size_t o = (size_t)which * (T_*D_)
                             + (((size_t)(b_*H_ + h_) * S_ + s_) << 6) + d_;
                    float x0 = rr ? v2 : v0, x1 = rr ? v3 : v1;
                    uint32_t lo;
                    uint32_t hi = pack_hilo(x0, x1, lo);
                    *(uint32_t*)(Ch + o) = hi;
                    *(uint32_t*)(Cl + o) = lo;
                }
            }
        }
    }
}

// ---------------- embedding ----------------
__global__ void embed_kernel(const int* __restrict__ ids,
                             const float* __restrict__ emb,
                             const float* __restrict__ pe,
                             float* __restrict__ x) {
    int idx = blockIdx.x * blockDim.x + threadIdx.x;
    int t = idx >> 10;
    int d = idx & (D_ - 1);
    int s = t & (S_ - 1);
    x[idx] = emb[(size_t)ids[t] * D_ + d] * 32.0f + pe[s * D_ + d];
}

// ---------------- layernorm ----------------
__device__ __forceinline__ float block_sum(float v, float* red, float* bcast) {
    #pragma unroll
    for (int o = 16; o; o >>= 1) v += __shfl_xor_sync(0xffffffffu, v, o);
    if ((threadIdx.x & 31) == 0) red[threadIdx.x >> 5] = v;
    __syncthreads();
    if (threadIdx.x == 0) {
        float t = 0.f;
        #pragma unroll
        for (int i = 0; i < 8; i++) t += red[i];
        *bcast = t;
    }
    __syncthreads();
    float r = *bcast;
    __syncthreads();
    return r;
}

template<int OUT>
__global__ void ln_kernel(const float* __restrict__ x,
                          const float* __restrict__ gam,
                          const float* __restrict__ bet,
                          float* __restrict__ y,
                          __nv_bfloat16* __restrict__ yh,
                          __nv_bfloat16* __restrict__ yl) {
    __shared__ float red[8];
    __shared__ float bcast;
    int row = blockIdx.x;
    const float* xr = x + (size_t)row * D_;
    float4 xv = *reinterpret_cast<const float4*>(&xr[threadIdx.x * 4]);

    float s = xv.x + xv.y + xv.z + xv.w;
    float mean = block_sum(s, red, &bcast) * (1.0f / D_);

    float dx = xv.x - mean, dy = xv.y - mean, dz = xv.z - mean, dw = xv.w - mean;
    float sq = dx*dx + dy*dy + dz*dz + dw*dw;
    float var = block_sum(sq, red, &bcast) * (1.0f / D_);
    float inv = rsqrtf(var + 1e-6f);

    float4 gv = *reinterpret_cast<const float4*>(&gam[threadIdx.x * 4]);
    float4 bv = *reinterpret_cast<const float4*>(&bet[threadIdx.x * 4]);
    float o0 = dx * inv * gv.x + bv.x;
    float o1 = dy * inv * gv.y + bv.y;
    float o2 = dz * inv * gv.z + bv.z;
    float o3 = dw * inv * gv.w + bv.w;
    size_t off = (size_t)row * D_ + threadIdx.x * 4;
    if (OUT == 0) {
        *reinterpret_cast<float4*>(&y[off]) = make_float4(o0, o1, o2, o3);
    } else {
        uint32_t l0, l1;
        uint32_t h0 = pack_hilo(o0, o1, l0);
        uint32_t h1 = pack_hilo(o2, o3, l1);
        *reinterpret_cast<uint2*>(yh + off) = make_uint2(h0, h1);
        *reinterpret_cast<uint2*>(yl + off) = make_uint2(l0, l1);
    }
}

// ---------------- tensor-core flash attention (3-term bf16, 2-stage, x4 ldmatrix) ----------------
#define AST2 144
#define ATB  (64*AST2)
#define QTB  (128*AST2)
#define STG  (4*ATB)
#define MOFF (2*QTB)
#define KVOFF (MOFF + 4096)
#define ASMEM (KVOFF + 2*STG)   // 114688

__global__ void __launch_bounds__(256) attn_tc(
    const __nv_bfloat16* __restrict__ qh, const __nv_bfloat16* __restrict__ ql,
    const __nv_bfloat16* __restrict__ kh, const __nv_bfloat16* __restrict__ kl,
    const __nv_bfloat16* __restrict__ vh, const __nv_bfloat16* __restrict__ vl,
    const float* __restrict__ mask,
    __nv_bfloat16* __restrict__ oh, __nv_bfloat16* __restrict__ ol)
{
    extern __shared__ __align__(128) char smem[];
    const uint32_t sb = smem_u32(smem);
    const int tid = threadIdx.x, lane = tid & 31, w = tid >> 5;
    const int bh = blockIdx.x, qt = blockIdx.y;
    const int b_ = bh >> 4, h_ = bh & 15;
    const int g = lane >> 2, t4 = lane & 3;
    const int lrow = lane & 7, lsel = lane >> 3;
    const float* Msm = (const float*)(smem + MOFF);

    // ---- Q (128x64 hi/lo) + mask ----
    const size_t qbase = ((size_t)bh * S_ + qt * 128) * 64;
    #pragma unroll
    for (int i = 0; i < 4; i++) {
        int idx = tid + i * 256;
        int r = idx >> 3, u = idx & 7;
        uint32_t so = r * AST2 + u * 16;
        size_t go = qbase + r * 64 + u * 8;
        CP16(sb + so,       qh + go);
        CP16(sb + QTB + so, ql + go);
    }
    CP16(sb + MOFF + tid * 16, mask + (size_t)b_ * S_ + tid * 4);
    CP_COMMIT();

    auto issue_stage = [&](int s, int buf) {
        const uint32_t d = sb + KVOFF + buf * STG;
        const size_t kb = ((size_t)bh * S_ + s * 64) * 64;
        #pragma unroll
        for (int i = 0; i < 2; i++) {
            int idx = tid + i * 256;
            int r = idx >> 3, u = idx & 7;
            uint32_t so = r * AST2 + u * 16;
            size_t go = kb + r * 64 + u * 8;
            CP16(d + so,         kh + go);
            CP16(d + ATB + so,   kl + go);
            CP16(d + 2*ATB + so, vh + go);
            CP16(d + 3*ATB + so, vl + go);
        }
    };

    issue_stage(0, 0); CP_COMMIT();
    CP_WAIT0();
    __syncthreads();

    uint32_t aqh[4][4], aql[4][4];
    const uint32_t qoff = sb + (uint32_t)((w * 16 + (lsel & 1) * 8 + lrow) * AST2 + (lsel >> 1) * 16);
    #pragma unroll
    for (int ks = 0; ks < 4; ks++) {
        LDSM4(aqh[ks], qoff + ks * 32);
        LDSM4(aql[ks], qoff + QTB + ks * 32);
    }

    float m0 = -1e30f, m1 = -1e30f, l0 = 0.f, l1 = 0.f;
    float o[8][4];
    #pragma unroll
    for (int i = 0; i < 8; i++)
        #pragma unroll
        for (int j = 0; j < 4; j++) o[i][j] = 0.f;

    #pragma unroll 1
    for (int kt = 0; kt < S_ / 64; kt++) {
        const int buf = kt & 1;
        if (kt + 1 < S_ / 64) { issue_stage(kt + 1, buf ^ 1); CP_COMMIT(); CP_WAIT1(); }
        else                  { CP_WAIT0(); }
        __syncthreads();

        const uint32_t base = sb + KVOFF + buf * STG;

        // ---- S = Q K^T (3-term), K via ldmatrix.x4 ----
        float sc[8][4];
        #pragma unroll
        for (int nt = 0; nt < 8; nt++)
            sc[nt][0] = sc[nt][1] = sc[nt][2] = sc[nt][3] = 0.f;
        #pragma unroll
        for (int ks = 0; ks < 4; ks++) {
            #pragma unroll
            for (int np = 0; np < 4; np++) {
                const uint32_t kaddr = base
                    + (uint32_t)((np * 16 + ((lane >> 4) & 1) * 8 + lrow) * AST2
                                 + ((lane >> 3) & 1) * 16 + ks * 32);
                uint32_t t4h[4], t4l[4];
                LDSM4(t4h, kaddr);
                LDSM4(t4l, kaddr + ATB);
                MMA2(sc[2*np],   aqh[ks], t4h[0], t4h[1]);
                MMA2(sc[2*np],   aqh[ks], t4l[0], t4l[1]);
                MMA2(sc[2*np],   aql[ks], t4h[0], t4h[1]);
                MMA2(sc[2*np+1], aqh[ks], t4h[2], t4h[3]);
                MMA2(sc[2*np+1], aqh[ks], t4l[2], t4l[3]);
                MMA2(sc[2*np+1], aql[ks], t4h[2], t4h[3]);
            }
        }

        // ---- scale + mask + online softmax ----
        float rmax0 = -1e30f, rmax1 = -1e30f;
        #pragma unroll
        for (int nt = 0; nt < 8; nt++) {
            int j = kt * 64 + nt * 8 + t4 * 2;
            float mk0 = Msm[j], mk1 = Msm[j + 1];
            sc[nt][0] = (mk0 == 0.f) ? -1e9f : sc[nt][0] * 0.125f;
            sc[nt][1] = (mk1 == 0.f) ? -1e9f : sc[nt][1] * 0.125f;
            sc[nt][2] = (mk0 == 0.f) ? -1e9f : sc[nt][2] * 0.125f;
            sc[nt][3] = (mk1 == 0.f) ? -1e9f : sc[nt][3] * 0.125f;
            rmax0 = fmaxf(rmax0, fmaxf(sc[nt][0], sc[nt][1]));
            rmax1 = fmaxf(rmax1, fmaxf(sc[nt][2], sc[nt][3]));
        }
        rmax0 = fmaxf(rmax0, __shfl_xor_sync(0xffffffffu, rmax0, 1));
        rmax0 = fmaxf(rmax0, __shfl_xor_sync(0xffffffffu, rmax0, 2));
        rmax1 = fmaxf(rmax1, __shfl_xor_sync(0xffffffffu, rmax1, 1));
        rmax1 = fmaxf(rmax1, __shfl_xor_sync(0xffffffffu, rmax1, 2));

        float mn0 = fmaxf(m0, rmax0), mn1 = fmaxf(m1, rmax1);
        float c0 = __expf(m0 - mn0), c1 = __expf(m1 - mn1);
        m0 = mn0; m1 = mn1;

        float ls0 = 0.f, ls1 = 0.f;
        #pragma unroll
        for (int nt = 0; nt < 8; nt++) {
            sc[nt][0] = __expf(sc[nt][0] - m0);
            sc[nt][1] = __expf(sc[nt][1] - m0);
            sc[nt][2] = __expf(sc[nt][2] - m1);
            sc[nt][3] = __expf(sc[nt][3] - m1);
            ls0 += sc[nt][0] + sc[nt][1];
            ls1 += sc[nt][2] + sc[nt][3];
        }
        l0 = l0 * c0 + ls0;
        l1 = l1 * c1 + ls1;

        #pragma unroll
        for (int nt = 0; nt < 8; nt++) {
            o[nt][0] *= c0; o[nt][1] *= c0;
            o[nt][2] *= c1; o[nt][3] *= c1;
        }

        // ---- O += P V (3-term), V via ldmatrix.x4.trans ----
        #pragma unroll
        for (int kc = 0; kc < 4; kc++) {
            uint32_t pah[4], pal[4];
            int n0t = 2 * kc, n1t = 2 * kc + 1;
            pah[0] = pack_hilo(sc[n0t][0], sc[n0t][1], pal[0]);
            pah[1] = pack_hilo(sc[n0t][2], sc[n0t][3], pal[1]);
            pah[2] = pack_hilo(sc[n1t][0], sc[n1t][1], pal[2]);
            pah[3] = pack_hilo(sc[n1t][2], sc[n1t][3], pal[3]);
            const uint32_t vrow = (uint32_t)(kc * 16 + (lane & 7) + ((lane >> 3) & 1) * 8);
            #pragma unroll
            for (int ndp = 0; ndp < 4; ndp++) {
                const uint32_t vaddr = base + 2*ATB
                    + vrow * AST2 + (uint32_t)((ndp * 2 + (lane >> 4)) * 16);
                uint32_t t4h[4], t4l[4];
                LDSM4T(t4h, vaddr);
                LDSM4T(t4l, vaddr + ATB);
                MMA2(o[2*ndp],   pah, t4h[0], t4h[1]);
                MMA2(o[2*ndp],   pah, t4l[0], t4l[1]);
                MMA2(o[2*ndp],   pal, t4h[0], t4h[1]);
                MMA2(o[2*ndp+1], pah, t4h[2], t4h[3]);
                MMA2(o[2*ndp+1], pah, t4l[2], t4l[3]);
                MMA2(o[2*ndp+1], pal, t4h[2], t4h[3]);
            }
        }
        __syncthreads();
    }

    l0 += __shfl_xor_sync(0xffffffffu, l0, 1);
    l0 += __shfl_xor_sync(0xffffffffu, l0, 2);
    l1 += __shfl_xor_sync(0xffffffffu, l1, 1);
    l1 += __shfl_xor_sync(0xffffffffu, l1, 2);
    float inv0 = 1.f / l0, inv1 = 1.f / l1;

    int tok0 = b_ * S_ + qt * 128 + w * 16 + g;
    #pragma unroll
    for (int nt = 0; nt < 8; nt++) {
        int col = h_ * 64 + nt * 8 + t4 * 2;
        uint32_t lo;
        uint32_t hi = pack_hilo(o[nt][0] * inv0, o[nt][1] * inv0, lo);
        *(uint32_t*)(oh + (size_t)tok0 * D_ + col) = hi;
        *(uint32_t*)(ol + (size_t)tok0 * D_ + col) = lo;
        hi = pack_hilo(o[nt][2] * inv1, o[nt][3] * inv1, lo);
        *(uint32_t*)(oh + (size_t)(tok0 + 8) * D_ + col) = hi;
        *(uint32_t*)(ol + (size_t)(tok0 + 8) * D_ + col) = lo;
    }
}

// ---------------- launch ----------------
extern "C" void kernel_launch(void* const* d_in, const int* in_sizes, int n_in,
                              void* d_out, int out_size) {
    const int*   ids   = (const int*)  d_in[0];
    const float* mask  = (const float*)d_in[1];
    const float* emb   = (const float*)d_in[2];
    const float* pe    = (const float*)d_in[3];
    const float* w_q   = (const float*)d_in[4];
    const float* w_k   = (const float*)d_in[5];
    const float* w_v   = (const float*)d_in[6];
    const float* w_o   = (const float*)d_in[7];
    const float* b_o   = (const float*)d_in[8];
    const float* w1    = (const float*)d_in[9];
    const float* b1    = (const float*)d_in[10];
    const float* w2    = (const float*)d_in[11];
    const float* b2    = (const float*)d_in[12];
    const float* ln1_s = (const float*)d_in[13];
    const float* ln1_b = (const float*)d_in[14];
    const float* ln2_s = (const float*)d_in[15];
    const float* ln2_b = (const float*)d_in[16];
    const float* lnf_s = (const float*)d_in[17];
    const float* lnf_b = (const float*)d_in[18];
    float* out = (float*)d_out;

    float *px;
    __nv_bfloat16 *pqkvh, *pqkvl, *phh, *phl, *paoh, *paol, *pffh, *pffl;
    __nv_bfloat16 *qkvTh, *qkvTl, *woTh, *woTl, *w1Th, *w1Tl, *w2Th, *w2Tl;
    cudaGetSymbolAddress((void**)&px,    g_x);
    cudaGetSymbolAddress((void**)&pqkvh, g_qkvh);
    cudaGetSymbolAddress((void**)&pqkvl, g_qkvl);
    cudaGetSymbolAddress((void**)&phh,   g_h_hi);
    cudaGetSymbolAddress((void**)&phl,   g_h_lo);
    cudaGetSymbolAddress((void**)&paoh,  g_ao_hi);
    cudaGetSymbolAddress((void**)&paol,  g_ao_lo);
    cudaGetSymbolAddress((void**)&pffh,  g_ff_hi);
    cudaGetSymbolAddress((void**)&pffl,  g_ff_lo);
    cudaGetSymbolAddress((void**)&qkvTh, g_qkvT_hi);
    cudaGetSymbolAddress((void**)&qkvTl, g_qkvT_lo);
    cudaGetSymbolAddress((void**)&woTh,  g_woT_hi);
    cudaGetSymbolAddress((void**)&woTl,  g_woT_lo);
    cudaGetSymbolAddress((void**)&w1Th,  g_w1T_hi);
    cudaGetSymbolAddress((void**)&w1Tl,  g_w1T_lo);
    cudaGetSymbolAddress((void**)&w2Th,  g_w2T_hi);
    cudaGetSymbolAddress((void**)&w2Tl,  g_w2T_lo);

    cudaFuncSetAttribute((const void*)mma_gemm<2>, cudaFuncAttributeMaxDynamicSharedMemorySize, GSMEM_BYTES);
    cudaFuncSetAttribute((const void*)mma_gemm<3>, cudaFuncAttributeMaxDynamicSharedMemorySize, GSMEM_BYTES);
    cudaFuncSetAttribute((const void*)mma_gemm<4>, cudaFuncAttributeMaxDynamicSharedMemorySize, GSMEM_BYTES);
    cudaFuncSetAttribute((const void*)attn_tc,     cudaFuncAttributeMaxDynamicSharedMemorySize, ASMEM);

    dim3 cb(32, 8);
    dim3 gQKV(3*D_ / 128, T_ / 128);
    dim3 gProj(D_ / 128, T_ / 128);
    dim3 gFF1(F_ / 128, T_ / 128);
    dim3 gAttn(B_ * H_, S_ / 128);

    // launch indices 0-4 below put mma_gemm<4> (l=0) at index 5 for ncu -s 5 -c 1
    embed_kernel<<<T_ * D_ / 256, 256>>>(ids, emb, pe, px);                                     // 0
    ln_kernel<1><<<T_, 256>>>(px, ln1_s, ln1_b, nullptr, phh, phl);                             // 1
    convT_qkv<<<dim3(32, 32, L_*3), cb>>>(w_q, w_k, w_v, qkvTh, qkvTl);                         // 2
    convT_kernel<<<dim3(32, 32, L_), cb>>>(w_o, woTh, woTl, D_, D_, (size_t)D_*D_, (size_t)D_*D_); // 3
    convT_kernel<<<dim3(128, 32, L_), cb>>>(w1, w1Th, w1Tl, D_, F_, (size_t)D_*F_, (size_t)D_*F_); // 4

    for (int l = 0; l < L_; l++) {
        if (l > 0)
            ln_kernel<1><<<T_, 256>>>(px, ln1_s + l * D_, ln1_b + l * D_, nullptr, phh, phl);

        mma_gemm<4><<<gQKV, 256, GSMEM_BYTES>>>(phh, phl,                                       // 5 (l=0)
            qkvTh + (size_t)l*3*D_*D_, qkvTl + (size_t)l*3*D_*D_,
            nullptr, nullptr, nullptr, pqkvh, pqkvl, T_, 3*D_, D_);

        attn_tc<<<gAttn, 256, ASMEM>>>(
            pqkvh,                   pqkvl,
            pqkvh + (size_t)T_*D_,   pqkvl + (size_t)T_*D_,
            pqkvh + (size_t)2*T_*D_, pqkvl + (size_t)2*T_*D_,
            mask, paoh, paol);

        mma_gemm<3><<<gProj, 256, GSMEM_BYTES>>>(paoh, paol,
            woTh + (size_t)l*D_*D_, woTl + (size_t)l*D_*D_,
            b_o + l * D_, px, px, nullptr, nullptr, T_, D_, D_);

        ln_kernel<1><<<T_, 256>>>(px, ln2_s + l * D_, ln2_b + l * D_, nullptr, phh, phl);

        mma_gemm<2><<<gFF1, 256, GSMEM_BYTES>>>(phh, phl,
            w1Th + (size_t)l*D_*F_, w1Tl + (size_t)l*D_*F_,
            b1 + l * F_, nullptr, nullptr, pffh, pffl, T_, F_, D_);

        if (l == 0)
            convT_kernel<<<dim3(32, 128, L_), cb>>>(w2, w2Th, w2Tl, F_, D_, (size_t)F_*D_, (size_t)F_*D_);

        mma_gemm<3><<<gProj, 256, GSMEM_BYTES>>>(pffh, pffl,
            w2Th + (size_t)l*F_*D_, w2Tl + (size_t)l*F_*D_,
            b2 + l * D_, px, px, nullptr, nullptr, T_, D_, F_);
    }

    ln_kernel<0><<<T_, 256>>>(px, lnf_s, lnf_b, out, nullptr, nullptr);
}

// round 13
// speedup vs baseline: 1.6664x; 1.6664x over previous
#include <cuda_runtime.h>
#include <cuda_bf16.h>
#include <cstdint>

#define L_ 6
#define D_ 1024
#define H_ 16
#define DK_ 64
#define F_ 4096
#define B_ 2
#define S_ 1024
#define T_ (B_*S_)

// ---------------- scratch (static device allocations) ----------------
__device__ float g_x  [T_*D_];
__device__ __nv_bfloat16 g_qkvh[3*T_*D_];
__device__ __nv_bfloat16 g_qkvl[3*T_*D_];
__device__ __nv_bfloat16 g_h_hi [T_*D_];
__device__ __nv_bfloat16 g_h_lo [T_*D_];
__device__ __nv_bfloat16 g_ao_hi[T_*D_];
__device__ __nv_bfloat16 g_ao_lo[T_*D_];
__device__ __nv_bfloat16 g_ff_hi[T_*F_];
__device__ __nv_bfloat16 g_ff_lo[T_*F_];

__device__ __nv_bfloat16 g_qkvT_hi[L_*3*D_*D_];
__device__ __nv_bfloat16 g_qkvT_lo[L_*3*D_*D_];
__device__ __nv_bfloat16 g_woT_hi [L_*D_*D_];
__device__ __nv_bfloat16 g_woT_lo [L_*D_*D_];
__device__ __nv_bfloat16 g_w1T_hi [L_*D_*F_];
__device__ __nv_bfloat16 g_w1T_lo [L_*D_*F_];
__device__ __nv_bfloat16 g_w2T_hi [L_*F_*D_];
__device__ __nv_bfloat16 g_w2T_lo [L_*F_*D_];

// ---------------- helpers ----------------
__device__ __forceinline__ uint32_t smem_u32(const void* p) {
    uint32_t a;
    asm("{ .reg .u64 t; cvta.to.shared.u64 t, %1; cvt.u32.u64 %0, t; }" : "=r"(a) : "l"(p));
    return a;
}
__device__ __forceinline__ uint32_t pack_hilo(float a, float b, uint32_t& lo) {
    __nv_bfloat16 ha = __float2bfloat16_rn(a);
    __nv_bfloat16 hb = __float2bfloat16_rn(b);
    __nv_bfloat16 la = __float2bfloat16_rn(a - __bfloat162float(ha));
    __nv_bfloat16 lb = __float2bfloat16_rn(b - __bfloat162float(hb));
    __nv_bfloat162 h2 = __halves2bfloat162(ha, hb);
    __nv_bfloat162 l2 = __halves2bfloat162(la, lb);
    lo = *reinterpret_cast<uint32_t*>(&l2);
    return *reinterpret_cast<uint32_t*>(&h2);
}

#define CP16(dst, src) \
    asm volatile("cp.async.ca.shared.global [%0], [%1], 16;" :: "r"(dst), "l"(src) : "memory")
#define CP_COMMIT() asm volatile("cp.async.commit_group;" ::: "memory")
#define CP_WAIT1()  asm volatile("cp.async.wait_group 1;"  ::: "memory")
#define CP_WAIT0()  asm volatile("cp.async.wait_group 0;"  ::: "memory")

#define LDSM4(r, addr) \
    asm volatile("ldmatrix.sync.aligned.m8n8.x4.shared.b16 {%0,%1,%2,%3}, [%4];" \
        : "=r"((r)[0]), "=r"((r)[1]), "=r"((r)[2]), "=r"((r)[3]) : "r"(addr))
#define LDSM2(r, addr) \
    asm volatile("ldmatrix.sync.aligned.m8n8.x2.shared.b16 {%0,%1}, [%2];" \
        : "=r"((r)[0]), "=r"((r)[1]) : "r"(addr))
#define LDSM2T(r, addr) \
    asm volatile("ldmatrix.sync.aligned.m8n8.x2.trans.shared.b16 {%0,%1}, [%2];" \
        : "=r"((r)[0]), "=r"((r)[1]) : "r"(addr))

#define MMA16816(c, a, b) \
    asm volatile("mma.sync.aligned.m16n8k16.row.col.f32.bf16.bf16.f32 " \
        "{%0,%1,%2,%3}, {%4,%5,%6,%7}, {%8,%9}, {%0,%1,%2,%3};" \
        : "+f"((c)[0]), "+f"((c)[1]), "+f"((c)[2]), "+f"((c)[3]) \
        : "r"((a)[0]), "r"((a)[1]), "r"((a)[2]), "r"((a)[3]), "r"((b)[0]), "r"((b)[1]))

// ---------------- weight transpose + hi/lo split ----------------
__global__ void convT_kernel(const float* __restrict__ in, __nv_bfloat16* __restrict__ hi,
                             __nv_bfloat16* __restrict__ lo, int K, int N,
                             size_t in_ls, size_t out_ls) {
    __shared__ float t[32][33];
    in += (size_t)blockIdx.z * in_ls;
    hi += (size_t)blockIdx.z * out_ls;
    lo += (size_t)blockIdx.z * out_ls;
    int n0 = blockIdx.x * 32, k0 = blockIdx.y * 32;
    int tx = threadIdx.x, ty = threadIdx.y;
    #pragma unroll
    for (int i = 0; i < 4; i++)
        t[ty + 8*i][tx] = in[(size_t)(k0 + ty + 8*i) * N + n0 + tx];
    __syncthreads();
    #pragma unroll
    for (int i = 0; i < 4; i++) {
        float v = t[tx][ty + 8*i];
        __nv_bfloat16 h = __float2bfloat16_rn(v);
        __nv_bfloat16 l = __float2bfloat16_rn(v - __bfloat162float(h));
        size_t o = (size_t)(n0 + ty + 8*i) * K + k0 + tx;
        hi[o] = h; lo[o] = l;
    }
}

__global__ void convT_qkv(const float* __restrict__ wq, const float* __restrict__ wk,
                          const float* __restrict__ wv,
                          __nv_bfloat16* __restrict__ hi, __nv_bfloat16* __restrict__ lo) {
    __shared__ float t[32][33];
    int zz = blockIdx.z;
    int l = zz / 3, which = zz % 3;
    const float* in = (which == 0 ? wq : which == 1 ? wk : wv) + (size_t)l * D_ * D_;
    size_t ob = (size_t)l * 3 * D_ * D_ + (size_t)which * D_ * D_;
    int n0 = blockIdx.x * 32, k0 = blockIdx.y * 32;
    int tx = threadIdx.x, ty = threadIdx.y;
    #pragma unroll
    for (int i = 0; i < 4; i++)
        t[ty + 8*i][tx] = in[(size_t)(k0 + ty + 8*i) * D_ + n0 + tx];
    __syncthreads();
    #pragma unroll
    for (int i = 0; i < 4; i++) {
        float v = t[tx][ty + 8*i];
        __nv_bfloat16 h = __float2bfloat16_rn(v);
        __nv_bfloat16 l2 = __float2bfloat16_rn(v - __bfloat162float(h));
        size_t o = ob + (size_t)(n0 + ty + 8*i) * D_ + k0 + tx;
        hi[o] = h; lo[o] = l2;
    }
}

// ---------------- bf16 tensor-core GEMM (3-term split), 128x128, 2-stage ----------------
#define RS 80
#define GTILE (128*RS)
#define GBUF  (4*GTILE)
#define GSMEM_BYTES (2*GBUF)

template<int MODE>
__global__ void __launch_bounds__(256) mma_gemm(
    const __nv_bfloat16* __restrict__ Ah, const __nv_bfloat16* __restrict__ Al,
    const __nv_bfloat16* __restrict__ Bh, const __nv_bfloat16* __restrict__ Bl,
    const float* __restrict__ bias, const float* __restrict__ res,
    float* __restrict__ C, __nv_bfloat16* __restrict__ Ch, __nv_bfloat16* __restrict__ Cl,
    int M, int N, int K)
{
    extern __shared__ __align__(128) char smem[];
    const uint32_t sb = smem_u32(smem);
    const int tid = threadIdx.x, lane = tid & 31, wid = tid >> 5;
    const int wm = wid >> 2, wn = wid & 3;
    const int bm = blockIdx.y * 128, bn = blockIdx.x * 128;

    const int r0 = tid >> 2, u = tid & 3;
    const int r1 = r0 + 64;

    float c[4][4][4];
    #pragma unroll
    for (int i = 0; i < 4; i++)
        #pragma unroll
        for (int j = 0; j < 4; j++)
            #pragma unroll
            for (int q = 0; q < 4; q++) c[i][j][q] = 0.f;

    const int NT = K >> 5;

    auto issue = [&](int kt, int buf) {
        const int k0 = kt << 5;
        uint32_t d = sb + buf * GBUF;
        const size_t ga0 = (size_t)(bm + r0) * K + k0 + u * 8;
        const size_t ga1 = (size_t)(bm + r1) * K + k0 + u * 8;
        const size_t gb0 = (size_t)(bn + r0) * K + k0 + u * 8;
        const size_t gb1 = (size_t)(bn + r1) * K + k0 + u * 8;
        const uint32_t o0 = r0 * RS + u * 16, o1 = r1 * RS + u * 16;
        CP16(d + o0,             Ah + ga0);  CP16(d + o1,             Ah + ga1);
        CP16(d + GTILE   + o0,   Al + ga0);  CP16(d + GTILE   + o1,   Al + ga1);
        CP16(d + 2*GTILE + o0,   Bh + gb0);  CP16(d + 2*GTILE + o1,   Bh + gb1);
        CP16(d + 3*GTILE + o0,   Bl + gb0);  CP16(d + 3*GTILE + o1,   Bl + gb1);
    };

    const int lrow = lane & 7;
    const int lsel = lane >> 3;
    const uint32_t aoff = (uint32_t)((wm * 64 + (lsel & 1) * 8 + lrow) * RS + (lsel >> 1) * 16);
    const uint32_t boff = (uint32_t)((wn * 32 + ((lane >> 4) & 1) * 8 + lrow) * RS + ((lane >> 3) & 1) * 16);

    issue(0, 0); CP_COMMIT();

    for (int kt = 0; kt < NT; kt++) {
        const int buf = kt & 1;
        if (kt + 1 < NT) { issue(kt + 1, buf ^ 1); CP_COMMIT(); CP_WAIT1(); }
        else             { CP_WAIT0(); }
        __syncthreads();

        const uint32_t base = sb + buf * GBUF;
        #pragma unroll
        for (int ks = 0; ks < 2; ks++) {
            uint32_t a_h[4][4], a_l[4][4], b_h[4][2], b_l[4][2];
            const uint32_t ka = base + aoff + ks * 32;
            #pragma unroll
            for (int mt = 0; mt < 4; mt++) {
                LDSM4(a_h[mt], ka + mt * (16 * RS));
                LDSM4(a_l[mt], ka + GTILE + mt * (16 * RS));
            }
            const uint32_t kb = base + 2*GTILE + boff + ks * 32;
            #pragma unroll
            for (int np = 0; np < 2; np++) {
                uint32_t t4h[4], t4l[4];
                LDSM4(t4h, kb + np * (16 * RS));
                LDSM4(t4l, kb + GTILE + np * (16 * RS));
                b_h[np*2][0]   = t4h[0]; b_h[np*2][1]   = t4h[1];
                b_h[np*2+1][0] = t4h[2]; b_h[np*2+1][1] = t4h[3];
                b_l[np*2][0]   = t4l[0]; b_l[np*2][1]   = t4l[1];
                b_l[np*2+1][0] = t4l[2]; b_l[np*2+1][1] = t4l[3];
            }
            #pragma unroll
            for (int mt = 0; mt < 4; mt++)
                #pragma unroll
                for (int nt = 0; nt < 4; nt++) {
                    MMA16816(c[mt][nt], a_h[mt], b_h[nt]);
                    MMA16816(c[mt][nt], a_h[mt], b_l[nt]);
                    MMA16816(c[mt][nt], a_l[mt], b_h[nt]);
                }
        }
        __syncthreads();
    }

    const int g = lane >> 2, t4 = lane & 3;
    #pragma unroll
    for (int mt = 0; mt < 4; mt++) {
        #pragma unroll
        for (int nt = 0; nt < 4; nt++) {
            int row = bm + wm * 64 + mt * 16 + g;
            int col = bn + wn * 32 + nt * 8 + t4 * 2;
            float v0 = c[mt][nt][0], v1 = c[mt][nt][1];
            float v2 = c[mt][nt][2], v3 = c[mt][nt][3];
            if (MODE == 2) {
                float b0 = bias[col], b1 = bias[col + 1];
                v0 = fmaxf(v0 + b0, 0.f); v1 = fmaxf(v1 + b1, 0.f);
                v2 = fmaxf(v2 + b0, 0.f); v3 = fmaxf(v3 + b1, 0.f);
                uint32_t lo0, lo1;
                uint32_t hi0 = pack_hilo(v0, v1, lo0);
                uint32_t hi1 = pack_hilo(v2, v3, lo1);
                size_t o0 = (size_t)row * N + col;
                size_t o1 = (size_t)(row + 8) * N + col;
                *(uint32_t*)(Ch + o0) = hi0; *(uint32_t*)(Cl + o0) = lo0;
                *(uint32_t*)(Ch + o1) = hi1; *(uint32_t*)(Cl + o1) = lo1;
            } else if (MODE == 3) {
                float b0 = bias[col], b1 = bias[col + 1];
                size_t o0 = (size_t)row * N + col;
                size_t o1 = (size_t)(row + 8) * N + col;
                float2 r0v = *(const float2*)(res + o0);
                float2 r1v = *(const float2*)(res + o1);
                *(float2*)(C + o0) = make_float2(v0 + b0 + r0v.x, v1 + b1 + r0v.y);
                *(float2*)(C + o1) = make_float2(v2 + b0 + r1v.x, v3 + b1 + r1v.y);
            } else {
                int which = col >> 10;
                int h_ = (col >> 6) & 15;
                int d_ = col & 63;
                #pragma unroll
                for (int rr = 0; rr < 2; rr++) {
                    int grow = row + rr * 8;
                    int b_ = grow >> 10, s_ = grow & 1023;
                    size_t o = (size_t)which * (T_*D_)
                             + (((size_t)(b_*H_ + h_) * S_ + s_) << 6) + d_;
                    float x0 = rr ? v2 : v0, x1 = rr ? v3 : v1;
                    uint32_t lo;
                    uint32_t hi = pack_hilo(x0, x1, lo);
                    *(uint32_t*)(Ch + o) = hi;
                    *(uint32_t*)(Cl + o) = lo;
                }
            }
        }
    }
}

// ---------------- embedding ----------------
__global__ void embed_kernel(const int* __restrict__ ids,
                             const float* __restrict__ emb,
                             const float* __restrict__ pe,
                             float* __restrict__ x) {
    int idx = blockIdx.x * blockDim.x + threadIdx.x;
    int t = idx >> 10;
    int d = idx & (D_ - 1);
    int s = t & (S_ - 1);
    x[idx] = emb[(size_t)ids[t] * D_ + d] * 32.0f + pe[s * D_ + d];
}

// ---------------- layernorm ----------------
__device__ __forceinline__ float block_sum(float v, float* red, float* bcast) {
    #pragma unroll
    for (int o = 16; o; o >>= 1) v += __shfl_xor_sync(0xffffffffu, v, o);
    if ((threadIdx.x & 31) == 0) red[threadIdx.x >> 5] = v;
    __syncthreads();
    if (threadIdx.x == 0) {
        float t = 0.f;
        #pragma unroll
        for (int i = 0; i < 8; i++) t += red[i];
        *bcast = t;
    }
    __syncthreads();
    float r = *bcast;
    __syncthreads();
    return r;
}

template<int OUT>
__global__ void ln_kernel(const float* __restrict__ x,
                          const float* __restrict__ gam,
                          const float* __restrict__ bet,
                          float* __restrict__ y,
                          __nv_bfloat16* __restrict__ yh,
                          __nv_bfloat16* __restrict__ yl) {
    __shared__ float red[8];
    __shared__ float bcast;
    int row = blockIdx.x;
    const float* xr = x + (size_t)row * D_;
    float4 xv = *reinterpret_cast<const float4*>(&xr[threadIdx.x * 4]);

    float s = xv.x + xv.y + xv.z + xv.w;
    float mean = block_sum(s, red, &bcast) * (1.0f / D_);

    float dx = xv.x - mean, dy = xv.y - mean, dz = xv.z - mean, dw = xv.w - mean;
    float sq = dx*dx + dy*dy + dz*dz + dw*dw;
    float var = block_sum(sq, red, &bcast) * (1.0f / D_);
    float inv = rsqrtf(var + 1e-6f);

    float4 gv = *reinterpret_cast<const float4*>(&gam[threadIdx.x * 4]);
    float4 bv = *reinterpret_cast<const float4*>(&bet[threadIdx.x * 4]);
    float o0 = dx * inv * gv.x + bv.x;
    float o1 = dy * inv * gv.y + bv.y;
    float o2 = dz * inv * gv.z + bv.z;
    float o3 = dw * inv * gv.w + bv.w;
    size_t off = (size_t)row * D_ + threadIdx.x * 4;
    if (OUT == 0) {
        *reinterpret_cast<float4*>(&y[off]) = make_float4(o0, o1, o2, o3);
    } else {
        uint32_t l0, l1;
        uint32_t h0 = pack_hilo(o0, o1, l0);
        uint32_t h1 = pack_hilo(o2, o3, l1);
        *reinterpret_cast<uint2*>(yh + off) = make_uint2(h0, h1);
        *reinterpret_cast<uint2*>(yl + off) = make_uint2(l0, l1);
    }
}

// ---------------- tensor-core flash attention (3-term bf16, 2-stage pipeline) ----------------
#define AST2 144
#define ATB  (64*AST2)
#define QTB  (128*AST2)
#define STG  (4*ATB)
#define MOFF (2*QTB)
#define KVOFF (MOFF + 4096)
#define ASMEM (KVOFF + 2*STG)   // 114688

__global__ void __launch_bounds__(256) attn_tc(
    const __nv_bfloat16* __restrict__ qh, const __nv_bfloat16* __restrict__ ql,
    const __nv_bfloat16* __restrict__ kh, const __nv_bfloat16* __restrict__ kl,
    const __nv_bfloat16* __restrict__ vh, const __nv_bfloat16* __restrict__ vl,
    const float* __restrict__ mask,
    __nv_bfloat16* __restrict__ oh, __nv_bfloat16* __restrict__ ol)
{
    extern __shared__ __align__(128) char smem[];
    const uint32_t sb = smem_u32(smem);
    const int tid = threadIdx.x, lane = tid & 31, w = tid >> 5;
    const int bh = blockIdx.x, qt = blockIdx.y;
    const int b_ = bh >> 4, h_ = bh & 15;
    const int g = lane >> 2, t4 = lane & 3;
    const int lrow = lane & 7, lsel = lane >> 3;
    const float* Msm = (const float*)(smem + MOFF);

    // ---- Q (128x64 hi/lo) + mask ----
    const size_t qbase = ((size_t)bh * S_ + qt * 128) * 64;
    #pragma unroll
    for (int i = 0; i < 4; i++) {
        int idx = tid + i * 256;
        int r = idx >> 3, u = idx & 7;
        uint32_t so = r * AST2 + u * 16;
        size_t go = qbase + r * 64 + u * 8;
        CP16(sb + so,       qh + go);
        CP16(sb + QTB + so, ql + go);
    }
    CP16(sb + MOFF + tid * 16, mask + (size_t)b_ * S_ + tid * 4);
    CP_COMMIT();

    auto issue_stage = [&](int s, int buf) {
        const uint32_t d = sb + KVOFF + buf * STG;
        const size_t kb = ((size_t)bh * S_ + s * 64) * 64;
        #pragma unroll
        for (int i = 0; i < 2; i++) {
            int idx = tid + i * 256;
            int r = idx >> 3, u = idx & 7;
            uint32_t so = r * AST2 + u * 16;
            size_t go = kb + r * 64 + u * 8;
            CP16(d + so,         kh + go);
            CP16(d + ATB + so,   kl + go);
            CP16(d + 2*ATB + so, vh + go);
            CP16(d + 3*ATB + so, vl + go);
        }
    };

    issue_stage(0, 0); CP_COMMIT();
    CP_WAIT0();
    __syncthreads();

    uint32_t aqh[4][4], aql[4][4];
    const uint32_t qoff = sb + (uint32_t)((w * 16 + (lsel & 1) * 8 + lrow) * AST2 + (lsel >> 1) * 16);
    #pragma unroll
    for (int ks = 0; ks < 4; ks++) {
        LDSM4(aqh[ks], qoff + ks * 32);
        LDSM4(aql[ks], qoff + QTB + ks * 32);
    }

    float m0 = -1e30f, m1 = -1e30f, l0 = 0.f, l1 = 0.f;
    float o[8][4];
    #pragma unroll
    for (int i = 0; i < 8; i++)
        #pragma unroll
        for (int j = 0; j < 4; j++) o[i][j] = 0.f;

    #pragma unroll 1
    for (int kt = 0; kt < S_ / 64; kt++) {
        const int buf = kt & 1;
        if (kt + 1 < S_ / 64) { issue_stage(kt + 1, buf ^ 1); CP_COMMIT(); CP_WAIT1(); }
        else                  { CP_WAIT0(); }
        __syncthreads();

        const uint32_t base = sb + KVOFF + buf * STG;

        // ---- S = Q K^T (3-term) ----
        float sc[8][4];
        #pragma unroll
        for (int nt = 0; nt < 8; nt++) {
            sc[nt][0] = sc[nt][1] = sc[nt][2] = sc[nt][3] = 0.f;
            const uint32_t kaddr = base
                + (uint32_t)((nt * 8 + lrow) * AST2 + ((lane >> 3) & 1) * 16);
            #pragma unroll
            for (int ks = 0; ks < 4; ks++) {
                uint32_t bkh[2], bkl[2];
                LDSM2(bkh, kaddr + ks * 32);
                LDSM2(bkl, kaddr + ATB + ks * 32);
                MMA16816(sc[nt], aqh[ks], bkh);
                MMA16816(sc[nt], aqh[ks], bkl);
                MMA16816(sc[nt], aql[ks], bkh);
            }
        }

        // ---- scale + mask + online softmax ----
        float rmax0 = -1e30f, rmax1 = -1e30f;
        #pragma unroll
        for (int nt = 0; nt < 8; nt++) {
            int j = kt * 64 + nt * 8 + t4 * 2;
            float mk0 = Msm[j], mk1 = Msm[j + 1];
            sc[nt][0] = (mk0 == 0.f) ? -1e9f : sc[nt][0] * 0.125f;
            sc[nt][1] = (mk1 == 0.f) ? -1e9f : sc[nt][1] * 0.125f;
            sc[nt][2] = (mk0 == 0.f) ? -1e9f : sc[nt][2] * 0.125f;
            sc[nt][3] = (mk1 == 0.f) ? -1e9f : sc[nt][3] * 0.125f;
            rmax0 = fmaxf(rmax0, fmaxf(sc[nt][0], sc[nt][1]));
            rmax1 = fmaxf(rmax1, fmaxf(sc[nt][2], sc[nt][3]));
        }
        rmax0 = fmaxf(rmax0, __shfl_xor_sync(0xffffffffu, rmax0, 1));
        rmax0 = fmaxf(rmax0, __shfl_xor_sync(0xffffffffu, rmax0, 2));
        rmax1 = fmaxf(rmax1, __shfl_xor_sync(0xffffffffu, rmax1, 1));
        rmax1 = fmaxf(rmax1, __shfl_xor_sync(0xffffffffu, rmax1, 2));

        float mn0 = fmaxf(m0, rmax0), mn1 = fmaxf(m1, rmax1);
        float c0 = __expf(m0 - mn0), c1 = __expf(m1 - mn1);
        m0 = mn0; m1 = mn1;

        float ls0 = 0.f, ls1 = 0.f;
        #pragma unroll
        for (int nt = 0; nt < 8; nt++) {
            sc[nt][0] = __expf(sc[nt][0] - m0);
            sc[nt][1] = __expf(sc[nt][1] - m0);
            sc[nt][2] = __expf(sc[nt][2] - m1);
            sc[nt][3] = __expf(sc[nt][3] - m1);
            ls0 += sc[nt][0] + sc[nt][1];
            ls1 += sc[nt][2] + sc[nt][3];
        }
        l0 = l0 * c0 + ls0;
        l1 = l1 * c1 + ls1;

        #pragma unroll
        for (int nt = 0; nt < 8; nt++) {
            o[nt][0] *= c0; o[nt][1] *= c0;
            o[nt][2] *= c1; o[nt][3] *= c1;
        }

        // ---- O += P V (3-term) ----
        #pragma unroll
        for (int kc = 0; kc < 4; kc++) {
            uint32_t pah[4], pal[4];
            int n0t = 2 * kc, n1t = 2 * kc + 1;
            pah[0] = pack_hilo(sc[n0t][0], sc[n0t][1], pal[0]);
            pah[1] = pack_hilo(sc[n0t][2], sc[n0t][3], pal[1]);
            pah[2] = pack_hilo(sc[n1t][0], sc[n1t][1], pal[2]);
            pah[3] = pack_hilo(sc[n1t][2], sc[n1t][3], pal[3]);
            const uint32_t vbase = base + 2*ATB + (uint32_t)((kc * 16 + (lane & 15)) * AST2);
            #pragma unroll
            for (int nd = 0; nd < 8; nd++) {
                uint32_t bvh[2], bvl[2];
                LDSM2T(bvh, vbase + nd * 16);
                LDSM2T(bvl, vbase + ATB + nd * 16);
                MMA16816(o[nd], pah, bvh);
                MMA16816(o[nd], pah, bvl);
                MMA16816(o[nd], pal, bvh);
            }
        }
        __syncthreads();
    }

    l0 += __shfl_xor_sync(0xffffffffu, l0, 1);
    l0 += __shfl_xor_sync(0xffffffffu, l0, 2);
    l1 += __shfl_xor_sync(0xffffffffu, l1, 1);
    l1 += __shfl_xor_sync(0xffffffffu, l1, 2);
    float inv0 = 1.f / l0, inv1 = 1.f / l1;

    int tok0 = b_ * S_ + qt * 128 + w * 16 + g;
    #pragma unroll
    for (int nt = 0; nt < 8; nt++) {
        int col = h_ * 64 + nt * 8 + t4 * 2;
        uint32_t lo;
        uint32_t hi = pack_hilo(o[nt][0] * inv0, o[nt][1] * inv0, lo);
        *(uint32_t*)(oh + (size_t)tok0 * D_ + col) = hi;
        *(uint32_t*)(ol + (size_t)tok0 * D_ + col) = lo;
        hi = pack_hilo(o[nt][2] * inv1, o[nt][3] * inv1, lo);
        *(uint32_t*)(oh + (size_t)(tok0 + 8) * D_ + col) = hi;
        *(uint32_t*)(ol + (size_t)(tok0 + 8) * D_ + col) = lo;
    }
}

// ---------------- launch ----------------
extern "C" void kernel_launch(void* const* d_in, const int* in_sizes, int n_in,
                              void* d_out, int out_size) {
    const int*   ids   = (const int*)  d_in[0];
    const float* mask  = (const float*)d_in[1];
    const float* emb   = (const float*)d_in[2];
    const float* pe    = (const float*)d_in[3];
    const float* w_q   = (const float*)d_in[4];
    const float* w_k   = (const float*)d_in[5];
    const float* w_v   = (const float*)d_in[6];
    const float* w_o   = (const float*)d_in[7];
    const float* b_o   = (const float*)d_in[8];
    const float* w1    = (const float*)d_in[9];
    const float* b1    = (const float*)d_in[10];
    const float* w2    = (const float*)d_in[11];
    const float* b2    = (const float*)d_in[12];
    const float* ln1_s = (const float*)d_in[13];
    const float* ln1_b = (const float*)d_in[14];
    const float* ln2_s = (const float*)d_in[15];
    const float* ln2_b = (const float*)d_in[16];
    const float* lnf_s = (const float*)d_in[17];
    const float* lnf_b = (const float*)d_in[18];
    float* out = (float*)d_out;

    float *px;
    __nv_bfloat16 *pqkvh, *pqkvl, *phh, *phl, *paoh, *paol, *pffh, *pffl;
    __nv_bfloat16 *qkvTh, *qkvTl, *woTh, *woTl, *w1Th, *w1Tl, *w2Th, *w2Tl;
    cudaGetSymbolAddress((void**)&px,    g_x);
    cudaGetSymbolAddress((void**)&pqkvh, g_qkvh);
    cudaGetSymbolAddress((void**)&pqkvl, g_qkvl);
    cudaGetSymbolAddress((void**)&phh,   g_h_hi);
    cudaGetSymbolAddress((void**)&phl,   g_h_lo);
    cudaGetSymbolAddress((void**)&paoh,  g_ao_hi);
    cudaGetSymbolAddress((void**)&paol,  g_ao_lo);
    cudaGetSymbolAddress((void**)&pffh,  g_ff_hi);
    cudaGetSymbolAddress((void**)&pffl,  g_ff_lo);
    cudaGetSymbolAddress((void**)&qkvTh, g_qkvT_hi);
    cudaGetSymbolAddress((void**)&qkvTl, g_qkvT_lo);
    cudaGetSymbolAddress((void**)&woTh,  g_woT_hi);
    cudaGetSymbolAddress((void**)&woTl,  g_woT_lo);
    cudaGetSymbolAddress((void**)&w1Th,  g_w1T_hi);
    cudaGetSymbolAddress((void**)&w1Tl,  g_w1T_lo);
    cudaGetSymbolAddress((void**)&w2Th,  g_w2T_hi);
    cudaGetSymbolAddress((void**)&w2Tl,  g_w2T_lo);

    cudaFuncSetAttribute((const void*)mma_gemm<2>, cudaFuncAttributeMaxDynamicSharedMemorySize, GSMEM_BYTES);
    cudaFuncSetAttribute((const void*)mma_gemm<3>, cudaFuncAttributeMaxDynamicSharedMemorySize, GSMEM_BYTES);
    cudaFuncSetAttribute((const void*)mma_gemm<4>, cudaFuncAttributeMaxDynamicSharedMemorySize, GSMEM_BYTES);
    cudaFuncSetAttribute((const void*)attn_tc,     cudaFuncAttributeMaxDynamicSharedMemorySize, ASMEM);

    dim3 cb(32, 8);
    dim3 gQKV(3*D_ / 128, T_ / 128);
    dim3 gProj(D_ / 128, T_ / 128);
    dim3 gFF1(F_ / 128, T_ / 128);
    dim3 gAttn(B_ * H_, S_ / 128);

    embed_kernel<<<T_ * D_ / 256, 256>>>(ids, emb, pe, px);                                     // 0
    ln_kernel<1><<<T_, 256>>>(px, ln1_s, ln1_b, nullptr, phh, phl);                             // 1
    convT_qkv<<<dim3(32, 32, L_*3), cb>>>(w_q, w_k, w_v, qkvTh, qkvTl);                         // 2
    convT_kernel<<<dim3(32, 32, L_), cb>>>(w_o, woTh, woTl, D_, D_, (size_t)D_*D_, (size_t)D_*D_); // 3
    convT_kernel<<<dim3(128, 32, L_), cb>>>(w1, w1Th, w1Tl, D_, F_, (size_t)D_*F_, (size_t)D_*F_); // 4

    for (int l = 0; l < L_; l++) {
        if (l > 0)
            ln_kernel<1><<<T_, 256>>>(px, ln1_s + l * D_, ln1_b + l * D_, nullptr, phh, phl);

        mma_gemm<4><<<gQKV, 256, GSMEM_BYTES>>>(phh, phl,                                       // 5 (l=0)
            qkvTh + (size_t)l*3*D_*D_, qkvTl + (size_t)l*3*D_*D_,
            nullptr, nullptr, nullptr, pqkvh, pqkvl, T_, 3*D_, D_);

        attn_tc<<<gAttn, 256, ASMEM>>>(
            pqkvh,                   pqkvl,
            pqkvh + (size_t)T_*D_,   pqkvl + (size_t)T_*D_,
            pqkvh + (size_t)2*T_*D_, pqkvl + (size_t)2*T_*D_,
            mask, paoh, paol);

        mma_gemm<3><<<gProj, 256, GSMEM_BYTES>>>(paoh, paol,
            woTh + (size_t)l*D_*D_, woTl + (size_t)l*D_*D_,
            b_o + l * D_, px, px, nullptr, nullptr, T_, D_, D_);

        ln_kernel<1><<<T_, 256>>>(px, ln2_s + l * D_, ln2_b + l * D_, nullptr, phh, phl);

        mma_gemm<2><<<gFF1, 256, GSMEM_BYTES>>>(phh, phl,
            w1Th + (size_t)l*D_*F_, w1Tl + (size_t)l*D_*F_,
            b1 + l * F_, nullptr, nullptr, pffh, pffl, T_, F_, D_);

        if (l == 0)
            convT_kernel<<<dim3(32, 128, L_), cb>>>(w2, w2Th, w2Tl, F_, D_, (size_t)F_*D_, (size_t)F_*D_);

        mma_gemm<3><<<gProj, 256, GSMEM_BYTES>>>(pffh, pffl,
            w2Th + (size_t)l*F_*D_, w2Tl + (size_t)l*F_*D_,
            b2 + l * D_, px, px, nullptr, nullptr, T_, D_, F_);
    }

    ln_kernel<0><<<T_, 256>>>(px, lnf_s, lnf_b, out, nullptr, nullptr);
}

// round 15
// speedup vs baseline: 1.7883x; 1.0731x over previous
#include <cuda_runtime.h>
#include <cuda_bf16.h>
#include <cstdint>

#define L_ 6
#define D_ 1024
#define H_ 16
#define DK_ 64
#define F_ 4096
#define B_ 2
#define S_ 1024
#define T_ (B_*S_)

// ---------------- scratch (static device allocations) ----------------
__device__ float g_x  [T_*D_];
__device__ float g_part[2*T_*D_];            // split-K partials
__device__ __nv_bfloat16 g_qkvh[3*T_*D_];
__device__ __nv_bfloat16 g_qkvl[3*T_*D_];
__device__ __nv_bfloat16 g_h_hi [T_*D_];
__device__ __nv_bfloat16 g_h_lo [T_*D_];
__device__ __nv_bfloat16 g_ao_hi[T_*D_];
__device__ __nv_bfloat16 g_ao_lo[T_*D_];
__device__ __nv_bfloat16 g_ff_hi[T_*F_];
__device__ __nv_bfloat16 g_ff_lo[T_*F_];

__device__ __nv_bfloat16 g_qkvT_hi[L_*3*D_*D_];
__device__ __nv_bfloat16 g_qkvT_lo[L_*3*D_*D_];
__device__ __nv_bfloat16 g_woT_hi [L_*D_*D_];
__device__ __nv_bfloat16 g_woT_lo [L_*D_*D_];
__device__ __nv_bfloat16 g_w1T_hi [L_*D_*F_];
__device__ __nv_bfloat16 g_w1T_lo [L_*D_*F_];
__device__ __nv_bfloat16 g_w2T_hi [L_*F_*D_];
__device__ __nv_bfloat16 g_w2T_lo [L_*F_*D_];

// ---------------- helpers ----------------
__device__ __forceinline__ uint32_t smem_u32(const void* p) {
    uint32_t a;
    asm("{ .reg .u64 t; cvta.to.shared.u64 t, %1; cvt.u32.u64 %0, t; }" : "=r"(a) : "l"(p));
    return a;
}
__device__ __forceinline__ uint32_t pack_hilo(float a, float b, uint32_t& lo) {
    __nv_bfloat16 ha = __float2bfloat16_rn(a);
    __nv_bfloat16 hb = __float2bfloat16_rn(b);
    __nv_bfloat16 la = __float2bfloat16_rn(a - __bfloat162float(ha));
    __nv_bfloat16 lb = __float2bfloat16_rn(b - __bfloat162float(hb));
    __nv_bfloat162 h2 = __halves2bfloat162(ha, hb);
    __nv_bfloat162 l2 = __halves2bfloat162(la, lb);
    lo = *reinterpret_cast<uint32_t*>(&l2);
    return *reinterpret_cast<uint32_t*>(&h2);
}

#define CP16(dst, src) \
    asm volatile("cp.async.ca.shared.global [%0], [%1], 16;" :: "r"(dst), "l"(src) : "memory")
#define CP_COMMIT() asm volatile("cp.async.commit_group;" ::: "memory")
#define CP_WAIT1()  asm volatile("cp.async.wait_group 1;"  ::: "memory")
#define CP_WAIT0()  asm volatile("cp.async.wait_group 0;"  ::: "memory")

#define LDSM4(r, addr) \
    asm volatile("ldmatrix.sync.aligned.m8n8.x4.shared.b16 {%0,%1,%2,%3}, [%4];" \
        : "=r"((r)[0]), "=r"((r)[1]), "=r"((r)[2]), "=r"((r)[3]) : "r"(addr))
#define LDSM2(r, addr) \
    asm volatile("ldmatrix.sync.aligned.m8n8.x2.shared.b16 {%0,%1}, [%2];" \
        : "=r"((r)[0]), "=r"((r)[1]) : "r"(addr))
#define LDSM2T(r, addr) \
    asm volatile("ldmatrix.sync.aligned.m8n8.x2.trans.shared.b16 {%0,%1}, [%2];" \
        : "=r"((r)[0]), "=r"((r)[1]) : "r"(addr))

#define MMA16816(c, a, b) \
    asm volatile("mma.sync.aligned.m16n8k16.row.col.f32.bf16.bf16.f32 " \
        "{%0,%1,%2,%3}, {%4,%5,%6,%7}, {%8,%9}, {%0,%1,%2,%3};" \
        : "+f"((c)[0]), "+f"((c)[1]), "+f"((c)[2]), "+f"((c)[3]) \
        : "r"((a)[0]), "r"((a)[1]), "r"((a)[2]), "r"((a)[3]), "r"((b)[0]), "r"((b)[1]))

// ---------------- weight transpose + hi/lo split ----------------
__global__ void convT_kernel(const float* __restrict__ in, __nv_bfloat16* __restrict__ hi,
                             __nv_bfloat16* __restrict__ lo, int K, int N,
                             size_t in_ls, size_t out_ls) {
    __shared__ float t[32][33];
    in += (size_t)blockIdx.z * in_ls;
    hi += (size_t)blockIdx.z * out_ls;
    lo += (size_t)blockIdx.z * out_ls;
    int n0 = blockIdx.x * 32, k0 = blockIdx.y * 32;
    int tx = threadIdx.x, ty = threadIdx.y;
    #pragma unroll
    for (int i = 0; i < 4; i++)
        t[ty + 8*i][tx] = in[(size_t)(k0 + ty + 8*i) * N + n0 + tx];
    __syncthreads();
    #pragma unroll
    for (int i = 0; i < 4; i++) {
        float v = t[tx][ty + 8*i];
        __nv_bfloat16 h = __float2bfloat16_rn(v);
        __nv_bfloat16 l = __float2bfloat16_rn(v - __bfloat162float(h));
        size_t o = (size_t)(n0 + ty + 8*i) * K + k0 + tx;
        hi[o] = h; lo[o] = l;
    }
}

__global__ void convT_qkv(const float* __restrict__ wq, const float* __restrict__ wk,
                          const float* __restrict__ wv,
                          __nv_bfloat16* __restrict__ hi, __nv_bfloat16* __restrict__ lo) {
    __shared__ float t[32][33];
    int zz = blockIdx.z;
    int l = zz / 3, which = zz % 3;
    const float* in = (which == 0 ? wq : which == 1 ? wk : wv) + (size_t)l * D_ * D_;
    size_t ob = (size_t)l * 3 * D_ * D_ + (size_t)which * D_ * D_;
    int n0 = blockIdx.x * 32, k0 = blockIdx.y * 32;
    int tx = threadIdx.x, ty = threadIdx.y;
    #pragma unroll
    for (int i = 0; i < 4; i++)
        t[ty + 8*i][tx] = in[(size_t)(k0 + ty + 8*i) * D_ + n0 + tx];
    __syncthreads();
    #pragma unroll
    for (int i = 0; i < 4; i++) {
        float v = t[tx][ty + 8*i];
        __nv_bfloat16 h = __float2bfloat16_rn(v);
        __nv_bfloat16 l2 = __float2bfloat16_rn(v - __bfloat162float(h));
        size_t o = ob + (size_t)(n0 + ty + 8*i) * D_ + k0 + tx;
        hi[o] = h; lo[o] = l2;
    }
}

// ---------------- bf16 tensor-core GEMM (3-term split), 128x128, 2-stage ----------------
// MODE 0: raw partial store (split-K via blockIdx.z)  MODE 2: relu(+bias)->Ch/Cl
// MODE 4: QKV hi/lo head-scatter->Ch/Cl
#define RS 80
#define GTILE (128*RS)
#define GBUF  (4*GTILE)
#define GSMEM_BYTES (2*GBUF)

template<int MODE>
__global__ void __launch_bounds__(256) mma_gemm(
    const __nv_bfloat16* __restrict__ Ah, const __nv_bfloat16* __restrict__ Al,
    const __nv_bfloat16* __restrict__ Bh, const __nv_bfloat16* __restrict__ Bl,
    const float* __restrict__ bias,
    float* __restrict__ C, __nv_bfloat16* __restrict__ Ch, __nv_bfloat16* __restrict__ Cl,
    int M, int N, int K, int Ksplit)
{
    extern __shared__ __align__(128) char smem[];
    const uint32_t sb = smem_u32(smem);
    const int tid = threadIdx.x, lane = tid & 31, wid = tid >> 5;
    const int wm = wid >> 2, wn = wid & 3;
    const int bm = blockIdx.y * 128, bn = blockIdx.x * 128;
    const int koff = blockIdx.z * Ksplit;

    const int r0 = tid >> 2, u = tid & 3;
    const int r1 = r0 + 64;

    float c[4][4][4];
    #pragma unroll
    for (int i = 0; i < 4; i++)
        #pragma unroll
        for (int j = 0; j < 4; j++)
            #pragma unroll
            for (int q = 0; q < 4; q++) c[i][j][q] = 0.f;

    const int NT = Ksplit >> 5;

    auto issue = [&](int kt, int buf) {
        const int k0 = koff + (kt << 5);
        uint32_t d = sb + buf * GBUF;
        const size_t ga0 = (size_t)(bm + r0) * K + k0 + u * 8;
        const size_t ga1 = (size_t)(bm + r1) * K + k0 + u * 8;
        const size_t gb0 = (size_t)(bn + r0) * K + k0 + u * 8;
        const size_t gb1 = (size_t)(bn + r1) * K + k0 + u * 8;
        const uint32_t o0 = r0 * RS + u * 16, o1 = r1 * RS + u * 16;
        CP16(d + o0,             Ah + ga0);  CP16(d + o1,             Ah + ga1);
        CP16(d + GTILE   + o0,   Al + ga0);  CP16(d + GTILE   + o1,   Al + ga1);
        CP16(d + 2*GTILE + o0,   Bh + gb0);  CP16(d + 2*GTILE + o1,   Bh + gb1);
        CP16(d + 3*GTILE + o0,   Bl + gb0);  CP16(d + 3*GTILE + o1,   Bl + gb1);
    };

    const int lrow = lane & 7;
    const int lsel = lane >> 3;
    const uint32_t aoff = (uint32_t)((wm * 64 + (lsel & 1) * 8 + lrow) * RS + (lsel >> 1) * 16);
    const uint32_t boff = (uint32_t)((wn * 32 + ((lane >> 4) & 1) * 8 + lrow) * RS + ((lane >> 3) & 1) * 16);

    issue(0, 0); CP_COMMIT();

    for (int kt = 0; kt < NT; kt++) {
        const int buf = kt & 1;
        if (kt + 1 < NT) { issue(kt + 1, buf ^ 1); CP_COMMIT(); CP_WAIT1(); }
        else             { CP_WAIT0(); }
        __syncthreads();

        const uint32_t base = sb + buf * GBUF;
        #pragma unroll
        for (int ks = 0; ks < 2; ks++) {
            uint32_t a_h[4][4], a_l[4][4], b_h[4][2], b_l[4][2];
            const uint32_t ka = base + aoff + ks * 32;
            #pragma unroll
            for (int mt = 0; mt < 4; mt++) {
                LDSM4(a_h[mt], ka + mt * (16 * RS));
                LDSM4(a_l[mt], ka + GTILE + mt * (16 * RS));
            }
            const uint32_t kb = base + 2*GTILE + boff + ks * 32;
            #pragma unroll
            for (int np = 0; np < 2; np++) {
                uint32_t t4h[4], t4l[4];
                LDSM4(t4h, kb + np * (16 * RS));
                LDSM4(t4l, kb + GTILE + np * (16 * RS));
                b_h[np*2][0]   = t4h[0]; b_h[np*2][1]   = t4h[1];
                b_h[np*2+1][0] = t4h[2]; b_h[np*2+1][1] = t4h[3];
                b_l[np*2][0]   = t4l[0]; b_l[np*2][1]   = t4l[1];
                b_l[np*2+1][0] = t4l[2]; b_l[np*2+1][1] = t4l[3];
            }
            #pragma unroll
            for (int mt = 0; mt < 4; mt++)
                #pragma unroll
                for (int nt = 0; nt < 4; nt++) {
                    MMA16816(c[mt][nt], a_h[mt], b_h[nt]);
                    MMA16816(c[mt][nt], a_h[mt], b_l[nt]);
                    MMA16816(c[mt][nt], a_l[mt], b_h[nt]);
                }
        }
        __syncthreads();
    }

    const int g = lane >> 2, t4 = lane & 3;
    float* Cz = C + (MODE == 0 ? (size_t)blockIdx.z * (T_*D_) : 0);
    #pragma unroll
    for (int mt = 0; mt < 4; mt++) {
        #pragma unroll
        for (int nt = 0; nt < 4; nt++) {
            int row = bm + wm * 64 + mt * 16 + g;
            int col = bn + wn * 32 + nt * 8 + t4 * 2;
            float v0 = c[mt][nt][0], v1 = c[mt][nt][1];
            float v2 = c[mt][nt][2], v3 = c[mt][nt][3];
            if (MODE == 0) {
                size_t o0 = (size_t)row * N + col;
                size_t o1 = (size_t)(row + 8) * N + col;
                *(float2*)(Cz + o0) = make_float2(v0, v1);
                *(float2*)(Cz + o1) = make_float2(v2, v3);
            } else if (MODE == 2) {
                float b0 = bias[col], b1 = bias[col + 1];
                v0 = fmaxf(v0 + b0, 0.f); v1 = fmaxf(v1 + b1, 0.f);
                v2 = fmaxf(v2 + b0, 0.f); v3 = fmaxf(v3 + b1, 0.f);
                uint32_t lo0, lo1;
                uint32_t hi0 = pack_hilo(v0, v1, lo0);
                uint32_t hi1 = pack_hilo(v2, v3, lo1);
                size_t o0 = (size_t)row * N + col;
                size_t o1 = (size_t)(row + 8) * N + col;
                *(uint32_t*)(Ch + o0) = hi0; *(uint32_t*)(Cl + o0) = lo0;
                *(uint32_t*)(Ch + o1) = hi1; *(uint32_t*)(Cl + o1) = lo1;
            } else { // MODE 4
                int which = col >> 10;
                int h_ = (col >> 6) & 15;
                int d_ = col & 63;
                #pragma unroll
                for (int rr = 0; rr < 2; rr++) {
                    int grow = row + rr * 8;
                    int b_ = grow >> 10, s_ = grow & 1023;
                    size_t o = (size_t)which * (T_*D_)
                             + (((size_t)(b_*H_ + h_) * S_ + s_) << 6) + d_;
                    float x0 = rr ? v2 : v0, x1 = rr ? v3 : v1;
                    uint32_t lo;
                    uint32_t hi = pack_hilo(x0, x1, lo);
                    *(uint32_t*)(Ch + o) = hi;
                    *(uint32_t*)(Cl + o) = lo;
                }
            }
        }
    }
}

// ---------------- embedding ----------------
__global__ void embed_kernel(const int* __restrict__ ids,
                             const float* __restrict__ emb,
                             const float* __restrict__ pe,
                             float* __restrict__ x) {
    int idx = blockIdx.x * blockDim.x + threadIdx.x;
    int t = idx >> 10;
    int d = idx & (D_ - 1);
    int s = t & (S_ - 1);
    x[idx] = emb[(size_t)ids[t] * D_ + d] * 32.0f + pe[s * D_ + d];
}

// ---------------- layernorm ----------------
__device__ __forceinline__ float block_sum(float v, float* red, float* bcast) {
    #pragma unroll
    for (int o = 16; o; o >>= 1) v += __shfl_xor_sync(0xffffffffu, v, o);
    if ((threadIdx.x & 31) == 0) red[threadIdx.x >> 5] = v;
    __syncthreads();
    if (threadIdx.x == 0) {
        float t = 0.f;
        #pragma unroll
        for (int i = 0; i < 8; i++) t += red[i];
        *bcast = t;
    }
    __syncthreads();
    float r = *bcast;
    __syncthreads();
    return r;
}

// plain LN (used once after embed): OUT==1 bf16 hi/lo
__global__ void ln_kernel(const float* __restrict__ x,
                          const float* __restrict__ gam,
                          const float* __restrict__ bet,
                          __nv_bfloat16* __restrict__ yh,
                          __nv_bfloat16* __restrict__ yl) {
    __shared__ float red[8];
    __shared__ float bcast;
    int row = blockIdx.x;
    const float* xr = x + (size_t)row * D_;
    float4 xv = *reinterpret_cast<const float4*>(&xr[threadIdx.x * 4]);

    float s = xv.x + xv.y + xv.z + xv.w;
    float mean = block_sum(s, red, &bcast) * (1.0f / D_);
    float dx = xv.x - mean, dy = xv.y - mean, dz = xv.z - mean, dw = xv.w - mean;
    float var = block_sum(dx*dx + dy*dy + dz*dz + dw*dw, red, &bcast) * (1.0f / D_);
    float inv = rsqrtf(var + 1e-6f);

    float4 gv = *reinterpret_cast<const float4*>(&gam[threadIdx.x * 4]);
    float4 bv = *reinterpret_cast<const float4*>(&bet[threadIdx.x * 4]);
    float o0 = dx * inv * gv.x + bv.x;
    float o1 = dy * inv * gv.y + bv.y;
    float o2 = dz * inv * gv.z + bv.z;
    float o3 = dw * inv * gv.w + bv.w;
    size_t off = (size_t)row * D_ + threadIdx.x * 4;
    uint32_t l0, l1;
    uint32_t h0 = pack_hilo(o0, o1, l0);
    uint32_t h1 = pack_hilo(o2, o3, l1);
    *reinterpret_cast<uint2*>(yh + off) = make_uint2(h0, h1);
    *reinterpret_cast<uint2*>(yl + off) = make_uint2(l0, l1);
}

// fused split-K reduce + bias + residual + LN.
// x_new = p0 + p1 + bias + res ; writes x_new (if xout); LN(x_new) -> yh/yl (OUT=1) or y fp32 (OUT=0)
template<int OUT>
__global__ void ln_fused(const float* __restrict__ p0, const float* __restrict__ p1,
                         const float* __restrict__ res, const float* __restrict__ bias,
                         const float* __restrict__ gam, const float* __restrict__ bet,
                         float* __restrict__ xout, float* __restrict__ y,
                         __nv_bfloat16* __restrict__ yh, __nv_bfloat16* __restrict__ yl) {
    __shared__ float red[8];
    __shared__ float bcast;
    int row = blockIdx.x;
    size_t off = (size_t)row * D_ + threadIdx.x * 4;
    float4 a  = *reinterpret_cast<const float4*>(p0 + off);
    float4 b  = *reinterpret_cast<const float4*>(p1 + off);
    float4 r  = *reinterpret_cast<const float4*>(res + off);
    float4 bi = *reinterpret_cast<const float4*>(bias + threadIdx.x * 4);
    float x0 = a.x + b.x + bi.x + r.x;
    float x1 = a.y + b.y + bi.y + r.y;
    float x2 = a.z + b.z + bi.z + r.z;
    float x3 = a.w + b.w + bi.w + r.w;
    if (OUT == 1)
        *reinterpret_cast<float4*>(xout + off) = make_float4(x0, x1, x2, x3);

    float mean = block_sum(x0 + x1 + x2 + x3, red, &bcast) * (1.0f / D_);
    float dx = x0 - mean, dy = x1 - mean, dz = x2 - mean, dw = x3 - mean;
    float var = block_sum(dx*dx + dy*dy + dz*dz + dw*dw, red, &bcast) * (1.0f / D_);
    float inv = rsqrtf(var + 1e-6f);

    float4 gv = *reinterpret_cast<const float4*>(&gam[threadIdx.x * 4]);
    float4 bv = *reinterpret_cast<const float4*>(&bet[threadIdx.x * 4]);
    float o0 = dx * inv * gv.x + bv.x;
    float o1 = dy * inv * gv.y + bv.y;
    float o2 = dz * inv * gv.z + bv.z;
    float o3 = dw * inv * gv.w + bv.w;
    if (OUT == 0) {
        *reinterpret_cast<float4*>(y + off) = make_float4(o0, o1, o2, o3);
    } else {
        uint32_t l0, l1;
        uint32_t h0 = pack_hilo(o0, o1, l0);
        uint32_t h1 = pack_hilo(o2, o3, l1);
        *reinterpret_cast<uint2*>(yh + off) = make_uint2(h0, h1);
        *reinterpret_cast<uint2*>(yl + off) = make_uint2(l0, l1);
    }
}

// ---------------- tensor-core flash attention (3-term bf16, 2-stage pipeline) ----------------
#define AST2 144
#define ATB  (64*AST2)
#define QTB  (128*AST2)
#define STG  (4*ATB)
#define MOFF (2*QTB)
#define KVOFF (MOFF + 4096)
#define ASMEM (KVOFF + 2*STG)   // 114688

__global__ void __launch_bounds__(256) attn_tc(
    const __nv_bfloat16* __restrict__ qh, const __nv_bfloat16* __restrict__ ql,
    const __nv_bfloat16* __restrict__ kh, const __nv_bfloat16* __restrict__ kl,
    const __nv_bfloat16* __restrict__ vh, const __nv_bfloat16* __restrict__ vl,
    const float* __restrict__ mask,
    __nv_bfloat16* __restrict__ oh, __nv_bfloat16* __restrict__ ol)
{
    extern __shared__ __align__(128) char smem[];
    const uint32_t sb = smem_u32(smem);
    const int tid = threadIdx.x, lane = tid & 31, w = tid >> 5;
    const int bh = blockIdx.x, qt = blockIdx.y;
    const int b_ = bh >> 4, h_ = bh & 15;
    const int g = lane >> 2, t4 = lane & 3;
    const int lrow = lane & 7, lsel = lane >> 3;
    const float* Msm = (const float*)(smem + MOFF);

    const size_t qbase = ((size_t)bh * S_ + qt * 128) * 64;
    #pragma unroll
    for (int i = 0; i < 4; i++) {
        int idx = tid + i * 256;
        int r = idx >> 3, u = idx & 7;
        uint32_t so = r * AST2 + u * 16;
        size_t go = qbase + r * 64 + u * 8;
        CP16(sb + so,       qh + go);
        CP16(sb + QTB + so, ql + go);
    }
    CP16(sb + MOFF + tid * 16, mask + (size_t)b_ * S_ + tid * 4);
    CP_COMMIT();

    auto issue_stage = [&](int s, int buf) {
        const uint32_t d = sb + KVOFF + buf * STG;
        const size_t kb = ((size_t)bh * S_ + s * 64) * 64;
        #pragma unroll
        for (int i = 0; i < 2; i++) {
            int idx = tid + i * 256;
            int r = idx >> 3, u = idx & 7;
            uint32_t so = r * AST2 + u * 16;
            size_t go = kb + r * 64 + u * 8;
            CP16(d + so,         kh + go);
            CP16(d + ATB + so,   kl + go);
            CP16(d + 2*ATB + so, vh + go);
            CP16(d + 3*ATB + so, vl + go);
        }
    };

    issue_stage(0, 0); CP_COMMIT();
    CP_WAIT0();
    __syncthreads();

    uint32_t aqh[4][4], aql[4][4];
    const uint32_t qoff = sb + (uint32_t)((w * 16 + (lsel & 1) * 8 + lrow) * AST2 + (lsel >> 1) * 16);
    #pragma unroll
    for (int ks = 0; ks < 4; ks++) {
        LDSM4(aqh[ks], qoff + ks * 32);
        LDSM4(aql[ks], qoff + QTB + ks * 32);
    }

    float m0 = -1e30f, m1 = -1e30f, l0 = 0.f, l1 = 0.f;
    float o[8][4];
    #pragma unroll
    for (int i = 0; i < 8; i++)
        #pragma unroll
        for (int j = 0; j < 4; j++) o[i][j] = 0.f;

    #pragma unroll 1
    for (int kt = 0; kt < S_ / 64; kt++) {
        const int buf = kt & 1;
        if (kt + 1 < S_ / 64) { issue_stage(kt + 1, buf ^ 1); CP_COMMIT(); CP_WAIT1(); }
        else                  { CP_WAIT0(); }
        __syncthreads();

        const uint32_t base = sb + KVOFF + buf * STG;

        float sc[8][4];
        #pragma unroll
        for (int nt = 0; nt < 8; nt++) {
            sc[nt][0] = sc[nt][1] = sc[nt][2] = sc[nt][3] = 0.f;
            const uint32_t kaddr = base
                + (uint32_t)((nt * 8 + lrow) * AST2 + ((lane >> 3) & 1) * 16);
            #pragma unroll
            for (int ks = 0; ks < 4; ks++) {
                uint32_t bkh[2], bkl[2];
                LDSM2(bkh, kaddr + ks * 32);
                LDSM2(bkl, kaddr + ATB + ks * 32);
                MMA16816(sc[nt], aqh[ks], bkh);
                MMA16816(sc[nt], aqh[ks], bkl);
                MMA16816(sc[nt], aql[ks], bkh);
            }
        }

        float rmax0 = -1e30f, rmax1 = -1e30f;
        #pragma unroll
        for (int nt = 0; nt < 8; nt++) {
            int j = kt * 64 + nt * 8 + t4 * 2;
            float mk0 = Msm[j], mk1 = Msm[j + 1];
            sc[nt][0] = (mk0 == 0.f) ? -1e9f : sc[nt][0] * 0.125f;
            sc[nt][1] = (mk1 == 0.f) ? -1e9f : sc[nt][1] * 0.125f;
            sc[nt][2] = (mk0 == 0.f) ? -1e9f : sc[nt][2] * 0.125f;
            sc[nt][3] = (mk1 == 0.f) ? -1e9f : sc[nt][3] * 0.125f;
            rmax0 = fmaxf(rmax0, fmaxf(sc[nt][0], sc[nt][1]));
            rmax1 = fmaxf(rmax1, fmaxf(sc[nt][2], sc[nt][3]));
        }
        rmax0 = fmaxf(rmax0, __shfl_xor_sync(0xffffffffu, rmax0, 1));
        rmax0 = fmaxf(rmax0, __shfl_xor_sync(0xffffffffu, rmax0, 2));
        rmax1 = fmaxf(rmax1, __shfl_xor_sync(0xffffffffu, rmax1, 1));
        rmax1 = fmaxf(rmax1, __shfl_xor_sync(0xffffffffu, rmax1, 2));

        float mn0 = fmaxf(m0, rmax0), mn1 = fmaxf(m1, rmax1);
        float c0 = __expf(m0 - mn0), c1 = __expf(m1 - mn1);
        m0 = mn0; m1 = mn1;

        float ls0 = 0.f, ls1 = 0.f;
        #pragma unroll
        for (int nt = 0; nt < 8; nt++) {
            sc[nt][0] = __expf(sc[nt][0] - m0);
            sc[nt][1] = __expf(sc[nt][1] - m0);
            sc[nt][2] = __expf(sc[nt][2] - m1);
            sc[nt][3] = __expf(sc[nt][3] - m1);
            ls0 += sc[nt][0] + sc[nt][1];
            ls1 += sc[nt][2] + sc[nt][3];
        }
        l0 = l0 * c0 + ls0;
        l1 = l1 * c1 + ls1;

        #pragma unroll
        for (int nt = 0; nt < 8; nt++) {
            o[nt][0] *= c0; o[nt][1] *= c0;
            o[nt][2] *= c1; o[nt][3] *= c1;
        }

        #pragma unroll
        for (int kc = 0; kc < 4; kc++) {
            uint32_t pah[4], pal[4];
            int n0t = 2 * kc, n1t = 2 * kc + 1;
            pah[0] = pack_hilo(sc[n0t][0], sc[n0t][1], pal[0]);
            pah[1] = pack_hilo(sc[n0t][2], sc[n0t][3], pal[1]);
            pah[2] = pack_hilo(sc[n1t][0], sc[n1t][1], pal[2]);
            pah[3] = pack_hilo(sc[n1t][2], sc[n1t][3], pal[3]);
            const uint32_t vbase = base + 2*ATB + (uint32_t)((kc * 16 + (lane & 15)) * AST2);
            #pragma unroll
            for (int nd = 0; nd < 8; nd++) {
                uint32_t bvh[2], bvl[2];
                LDSM2T(bvh, vbase + nd * 16);
                LDSM2T(bvl, vbase + ATB + nd * 16);
                MMA16816(o[nd], pah, bvh);
                MMA16816(o[nd], pah, bvl);
                MMA16816(o[nd], pal, bvh);
            }
        }
        __syncthreads();
    }

    l0 += __shfl_xor_sync(0xffffffffu, l0, 1);
    l0 += __shfl_xor_sync(0xffffffffu, l0, 2);
    l1 += __shfl_xor_sync(0xffffffffu, l1, 1);
    l1 += __shfl_xor_sync(0xffffffffu, l1, 2);
    float inv0 = 1.f / l0, inv1 = 1.f / l1;

    int tok0 = b_ * S_ + qt * 128 + w * 16 + g;
    #pragma unroll
    for (int nt = 0; nt < 8; nt++) {
        int col = h_ * 64 + nt * 8 + t4 * 2;
        uint32_t lo;
        uint32_t hi = pack_hilo(o[nt][0] * inv0, o[nt][1] * inv0, lo);
        *(uint32_t*)(oh + (size_t)tok0 * D_ + col) = hi;
        *(uint32_t*)(ol + (size_t)tok0 * D_ + col) = lo;
        hi = pack_hilo(o[nt][2] * inv1, o[nt][3] * inv1, lo);
        *(uint32_t*)(oh + (size_t)(tok0 + 8) * D_ + col) = hi;
        *(uint32_t*)(ol + (size_t)(tok0 + 8) * D_ + col) = lo;
    }
}

// ---------------- launch ----------------
extern "C" void kernel_launch(void* const* d_in, const int* in_sizes, int n_in,
                              void* d_out, int out_size) {
    const int*   ids   = (const int*)  d_in[0];
    const float* mask  = (const float*)d_in[1];
    const float* emb   = (const float*)d_in[2];
    const float* pe    = (const float*)d_in[3];
    const float* w_q   = (const float*)d_in[4];
    const float* w_k   = (const float*)d_in[5];
    const float* w_v   = (const float*)d_in[6];
    const float* w_o   = (const float*)d_in[7];
    const float* b_o   = (const float*)d_in[8];
    const float* w1    = (const float*)d_in[9];
    const float* b1    = (const float*)d_in[10];
    const float* w2    = (const float*)d_in[11];
    const float* b2    = (const float*)d_in[12];
    const float* ln1_s = (const float*)d_in[13];
    const float* ln1_b = (const float*)d_in[14];
    const float* ln2_s = (const float*)d_in[15];
    const float* ln2_b = (const float*)d_in[16];
    const float* lnf_s = (const float*)d_in[17];
    const float* lnf_b = (const float*)d_in[18];
    float* out = (float*)d_out;

    float *px, *pp;
    __nv_bfloat16 *pqkvh, *pqkvl, *phh, *phl, *paoh, *paol, *pffh, *pffl;
    __nv_bfloat16 *qkvTh, *qkvTl, *woTh, *woTl, *w1Th, *w1Tl, *w2Th, *w2Tl;
    cudaGetSymbolAddress((void**)&px,    g_x);
    cudaGetSymbolAddress((void**)&pp,    g_part);
    cudaGetSymbolAddress((void**)&pqkvh, g_qkvh);
    cudaGetSymbolAddress((void**)&pqkvl, g_qkvl);
    cudaGetSymbolAddress((void**)&phh,   g_h_hi);
    cudaGetSymbolAddress((void**)&phl,   g_h_lo);
    cudaGetSymbolAddress((void**)&paoh,  g_ao_hi);
    cudaGetSymbolAddress((void**)&paol,  g_ao_lo);
    cudaGetSymbolAddress((void**)&pffh,  g_ff_hi);
    cudaGetSymbolAddress((void**)&pffl,  g_ff_lo);
    cudaGetSymbolAddress((void**)&qkvTh, g_qkvT_hi);
    cudaGetSymbolAddress((void**)&qkvTl, g_qkvT_lo);
    cudaGetSymbolAddress((void**)&woTh,  g_woT_hi);
    cudaGetSymbolAddress((void**)&woTl,  g_woT_lo);
    cudaGetSymbolAddress((void**)&w1Th,  g_w1T_hi);
    cudaGetSymbolAddress((void**)&w1Tl,  g_w1T_lo);
    cudaGetSymbolAddress((void**)&w2Th,  g_w2T_hi);
    cudaGetSymbolAddress((void**)&w2Tl,  g_w2T_lo);

    cudaFuncSetAttribute((const void*)mma_gemm<0>, cudaFuncAttributeMaxDynamicSharedMemorySize, GSMEM_BYTES);
    cudaFuncSetAttribute((const void*)mma_gemm<2>, cudaFuncAttributeMaxDynamicSharedMemorySize, GSMEM_BYTES);
    cudaFuncSetAttribute((const void*)mma_gemm<4>, cudaFuncAttributeMaxDynamicSharedMemorySize, GSMEM_BYTES);
    cudaFuncSetAttribute((const void*)attn_tc,     cudaFuncAttributeMaxDynamicSharedMemorySize, ASMEM);

    dim3 cb(32, 8);
    dim3 gQKV(3*D_ / 128, T_ / 128);         // (24,16)
    dim3 gProjS(D_ / 128, T_ / 128, 2);      // (8,16,2) split-K
    dim3 gFF1(F_ / 128, T_ / 128);           // (32,16)
    dim3 gAttn(B_ * H_, S_ / 128);

    embed_kernel<<<T_ * D_ / 256, 256>>>(ids, emb, pe, px);
    ln_kernel<<<T_, 256>>>(px, ln1_s, ln1_b, phh, phl);
    convT_qkv<<<dim3(32, 32, L_*3), cb>>>(w_q, w_k, w_v, qkvTh, qkvTl);
    convT_kernel<<<dim3(32, 32, L_), cb>>>(w_o, woTh, woTl, D_, D_, (size_t)D_*D_, (size_t)D_*D_);
    convT_kernel<<<dim3(128, 32, L_), cb>>>(w1, w1Th, w1Tl, D_, F_, (size_t)D_*F_, (size_t)D_*F_);

    for (int l = 0; l < L_; l++) {
        mma_gemm<4><<<gQKV, 256, GSMEM_BYTES>>>(phh, phl,
            qkvTh + (size_t)l*3*D_*D_, qkvTl + (size_t)l*3*D_*D_,
            nullptr, nullptr, pqkvh, pqkvl, T_, 3*D_, D_, D_);

        attn_tc<<<gAttn, 256, ASMEM>>>(
            pqkvh,                   pqkvl,
            pqkvh + (size_t)T_*D_,   pqkvl + (size_t)T_*D_,
            pqkvh + (size_t)2*T_*D_, pqkvl + (size_t)2*T_*D_,
            mask, paoh, paol);

        // wo GEMM, split-K=2 -> partials
        mma_gemm<0><<<gProjS, 256, GSMEM_BYTES>>>(paoh, paol,
            woTh + (size_t)l*D_*D_, woTl + (size_t)l*D_*D_,
            nullptr, pp, nullptr, nullptr, T_, D_, D_, D_/2);

        // fused: x += wo_out + b_o ; ln2 -> hi/lo
        ln_fused<1><<<T_, 256>>>(pp, pp + (size_t)T_*D_, px, b_o + l * D_,
                                 ln2_s + l * D_, ln2_b + l * D_,
                                 px, nullptr, phh, phl);

        mma_gemm<2><<<gFF1, 256, GSMEM_BYTES>>>(phh, phl,
            w1Th + (size_t)l*D_*F_, w1Tl + (size_t)l*D_*F_,
            b1 + l * F_, nullptr, pffh, pffl, T_, F_, D_, D_);

        if (l == 0)
            convT_kernel<<<dim3(32, 128, L_), cb>>>(w2, w2Th, w2Tl, F_, D_, (size_t)F_*D_, (size_t)F_*D_);

        // FF2 GEMM, split-K=2 -> partials
        mma_gemm<0><<<gProjS, 256, GSMEM_BYTES>>>(pffh, pffl,
            w2Th + (size_t)l*F_*D_, w2Tl + (size_t)l*F_*D_,
            nullptr, pp, nullptr, nullptr, T_, D_, F_, F_/2);

        if (l + 1 < L_) {
            // fused: x += ff2_out + b2 ; ln1(l+1) -> hi/lo
            ln_fused<1><<<T_, 256>>>(pp, pp + (size_t)T_*D_, px, b2 + l * D_,
                                     ln1_s + (l+1) * D_, ln1_b + (l+1) * D_,
                                     px, nullptr, phh, phl);
        } else {
            // fused: x += ff2_out + b2 ; final LN -> out (fp32)
            ln_fused<0><<<T_, 256>>>(pp, pp + (size_t)T_*D_, px, b2 + l * D_,
                                     lnf_s, lnf_b,
                                     nullptr, out, nullptr, nullptr);
        }
    }
}